// round 1
// baseline (speedup 1.0000x reference)
#include <cuda_runtime.h>
#include <math.h>

#define BATCH 8
#define LSEQ  1024
#define ROWS  (BATCH*LSEQ)   // 8192
#define DM    192
#define DI    384
#define DS    16
#define DTR   12
#define DBC_N (DTR + 2*DS)   // 44

// ---------------- scratch (static device globals; no runtime alloc) -------------
__device__ float g_Ape [ROWS*768];           // im2col of x           25.2 MB
__device__ float g_seq [ROWS*DM];            // patch-embed out        6.3 MB
__device__ float g_xz  [ROWS*2*DI];          // in_proj out           25.2 MB
__device__ float g_uact[ROWS*DI];            // conv1d+silu           12.6 MB
__device__ float g_dbc [ROWS*DBC_N];         // x_proj out             1.4 MB
__device__ float g_delta[ROWS*DI];           // softplus(dt_proj)     12.6 MB
__device__ float g_yg  [ROWS*DI];            // scan out (gated)      12.6 MB
__device__ float g_gout[ROWS*DM];            // out_proj out           6.3 MB
__device__ float g_dec [(size_t)BATCH*64*512*512];  // relu(deconv)  536.9 MB

// ---------------- im2col for 16x16 patch embedding ----------------------------
__global__ void im2col_kernel(const float* __restrict__ x) {
    int gid = blockIdx.x * 256 + threadIdx.x;
    if (gid >= ROWS * 768) return;
    int row = gid / 768, k = gid - row * 768;
    int c = k >> 8, rem = k & 255, p = rem >> 4, q = rem & 15;
    int b = row >> 10, hw = row & 1023, h = hw >> 5, w = hw & 31;
    g_Ape[gid] = x[((b * 3 + c) * 512 + h * 16 + p) * 512 + w * 16 + q];
}

// ---------------- generic 128x128x8 SGEMM, 8x8 per thread ----------------------
// BT=true : B is N x K row-major (computes A @ B^T)  -- "NT"
// BT=false: B is K x N row-major                      -- "NN"
// EPI=0: C[m*N+n] = acc + bias[n] (bias optional)
// EPI=1: deconv epilogue: relu(acc + bias[d]) scattered into g_dec layout
template<bool BT, int EPI>
__global__ __launch_bounds__(256)
void sgemm_kernel(const float* __restrict__ A, const float* __restrict__ B,
                  const float* __restrict__ bias, float* __restrict__ C,
                  int M, int N, int K)
{
    __shared__ float As[8][128];
    __shared__ float Bs[8][128];
    int tid = threadIdx.x;
    int bm = blockIdx.y * 128, bn = blockIdx.x * 128;
    int a_r = tid >> 1, a_k = (tid & 1) << 2;       // A (and B-NT) loader mapping
    int ty = tid >> 4, tx = tid & 15;               // compute mapping

    float acc[8][8];
#pragma unroll
    for (int i = 0; i < 8; i++)
#pragma unroll
        for (int j = 0; j < 8; j++) acc[i][j] = 0.f;

    for (int k0 = 0; k0 < K; k0 += 8) {
        // A tile (M rows always in-bounds here: M multiple of 128, K multiple of 8)
        float4 av = *(const float4*)(A + (size_t)(bm + a_r) * K + k0 + a_k);
        As[a_k + 0][a_r] = av.x; As[a_k + 1][a_r] = av.y;
        As[a_k + 2][a_r] = av.z; As[a_k + 3][a_r] = av.w;

        if (BT) {
            int n = bn + a_r;
            float4 bv = make_float4(0.f, 0.f, 0.f, 0.f);
            if (n < N) bv = *(const float4*)(B + (size_t)n * K + k0 + a_k);
            Bs[a_k + 0][a_r] = bv.x; Bs[a_k + 1][a_r] = bv.y;
            Bs[a_k + 2][a_r] = bv.z; Bs[a_k + 3][a_r] = bv.w;
        } else {
            int kk = tid >> 5, c4 = (tid & 31) << 2;
            int n = bn + c4;
            float4 bv = make_float4(0.f, 0.f, 0.f, 0.f);
            const float* bp = B + (size_t)(k0 + kk) * N + n;
            if (n + 3 < N) bv = *(const float4*)bp;
            else {
                if (n     < N) bv.x = bp[0];
                if (n + 1 < N) bv.y = bp[1];
                if (n + 2 < N) bv.z = bp[2];
            }
            *(float4*)&Bs[kk][c4] = bv;
        }
        __syncthreads();

#pragma unroll
        for (int kk = 0; kk < 8; kk++) {
            float4 a0 = *(const float4*)&As[kk][ty * 8];
            float4 a1 = *(const float4*)&As[kk][ty * 8 + 4];
            float4 b0 = *(const float4*)&Bs[kk][tx * 8];
            float4 b1 = *(const float4*)&Bs[kk][tx * 8 + 4];
            float ra[8] = {a0.x, a0.y, a0.z, a0.w, a1.x, a1.y, a1.z, a1.w};
            float rb[8] = {b0.x, b0.y, b0.z, b0.w, b1.x, b1.y, b1.z, b1.w};
#pragma unroll
            for (int i = 0; i < 8; i++)
#pragma unroll
                for (int j = 0; j < 8; j++)
                    acc[i][j] = fmaf(ra[i], rb[j], acc[i][j]);
        }
        __syncthreads();
    }

    if (EPI == 0) {
#pragma unroll
        for (int i = 0; i < 8; i++) {
            int m = bm + ty * 8 + i;
#pragma unroll
            for (int j = 0; j < 8; j++) {
                int n = bn + tx * 8 + j;
                if (n < N)
                    C[(size_t)m * N + n] = acc[i][j] + (bias ? bias[n] : 0.f);
            }
        }
    } else {
        // deconv scatter: m -> (b,h,w); n -> (d,p,q);  dst (b,d,16h+p,16w+q), relu
#pragma unroll
        for (int i = 0; i < 8; i++) {
            int m = bm + ty * 8 + i;
            int b = m >> 10, hw = m & 1023;
            size_t rowbase = (size_t)b * 16777216 + (size_t)(hw >> 5) * 8192 + (size_t)(hw & 31) * 16;
#pragma unroll
            for (int j = 0; j < 8; j++) {
                int n = bn + tx * 8 + j;
                int dch = n >> 8, p = (n >> 4) & 15, q = n & 15;
                float v = acc[i][j] + bias[dch];
                v = fmaxf(v, 0.f);
                C[rowbase + (size_t)dch * 262144 + p * 512 + q] = v;
            }
        }
    }
}

// ---------------- depthwise causal conv1d (k=4) + bias + silu -------------------
__global__ void conv1d_silu_kernel(const float* __restrict__ cw, const float* __restrict__ cb) {
    int gid = blockIdx.x * 256 + threadIdx.x;
    if (gid >= ROWS * DI) return;
    int idx = gid / DI, d = gid - idx * DI;
    int l = idx & 1023;
    float s = cb[d];
#pragma unroll
    for (int k = 0; k < 4; k++) {
        int ll = l - 3 + k;
        if (ll >= 0)
            s = fmaf(g_xz[(size_t)(idx - 3 + k) * 768 + d], cw[d * 4 + k], s);
    }
    g_uact[gid] = s / (1.f + expf(-s));   // silu
}

// ---------------- dt_proj + softplus -------------------------------------------
__global__ void dtproj_kernel(const float* __restrict__ dpw, const float* __restrict__ dpb) {
    int idx = blockIdx.x;        // row 0..8191
    int d = threadIdx.x;         // 0..383
    __shared__ float dts[DTR];
    if (d < DTR) dts[d] = g_dbc[idx * DBC_N + d];
    __syncthreads();
    float s = dpb[d];
#pragma unroll
    for (int r = 0; r < DTR; r++) s = fmaf(dts[r], dpw[d * DTR + r], s);
    // stable softplus
    g_delta[(size_t)idx * DI + d] = fmaxf(s, 0.f) + log1pf(expf(-fabsf(s)));
}

// ---------------- selective scan + C-projection + D skip + silu(z) gate --------
// one 16-lane group per (b, d) channel; lane = state index n
__global__ __launch_bounds__(256)
void scan_kernel(const float* __restrict__ A_log, const float* __restrict__ Dv) {
    int tid = threadIdx.x;
    int g = blockIdx.x * 16 + (tid >> 4);    // 0..3071
    int lane = tid & 15;
    int b = g / DI, d = g - b * DI;
    float An = -expf(A_log[d * DS + lane]);
    float Dd = Dv[d];
    float h = 0.f;
    int base = b * LSEQ;
    for (int l = 0; l < LSEQ; l++) {
        int idx = base + l;
        float delta = g_delta[(size_t)idx * DI + d];
        float uu    = g_uact [(size_t)idx * DI + d];
        float Bn    = g_dbc[idx * DBC_N + DTR + lane];
        float Cn    = g_dbc[idx * DBC_N + DTR + DS + lane];
        h = fmaf(expf(delta * An), h, delta * Bn * uu);
        float t = h * Cn;
        t += __shfl_xor_sync(0xffffffffu, t, 8);
        t += __shfl_xor_sync(0xffffffffu, t, 4);
        t += __shfl_xor_sync(0xffffffffu, t, 2);
        t += __shfl_xor_sync(0xffffffffu, t, 1);
        if (lane == 0) {
            float z = g_xz[(size_t)idx * 768 + DI + d];
            float y = fmaf(uu, Dd, t);
            g_yg[(size_t)idx * DI + d] = y * (z / (1.f + expf(-z)));
        }
    }
}

// ---------------- 3x3 conv (64->3, pad 1) + bias + sigmoid ---------------------
__global__ __launch_bounds__(256)
void conv3_sigmoid_kernel(const float* __restrict__ W, const float* __restrict__ wb,
                          float* __restrict__ out) {
    __shared__ float ws[3 * 64 * 9];       // 1728 floats
    __shared__ float tile[16][324];        // 16 channels x 18x18 halo tile
    int b = blockIdx.z, th = blockIdx.y, tw = blockIdx.x;
    int tid = threadIdx.x;
    for (int i = tid; i < 1728; i += 256) ws[i] = W[i];
    int py = tid >> 4, px = tid & 15;
    float a0 = wb[0], a1 = wb[1], a2 = wb[2];
    int y0 = th * 16 - 1, x0 = tw * 16 - 1;

    for (int c0 = 0; c0 < 64; c0 += 16) {
        __syncthreads();
        for (int i = tid; i < 16 * 324; i += 256) {
            int dl = i / 324, r = i - dl * 324;
            int yy = y0 + r / 18, xx = x0 + (r % 18);
            float v = 0.f;
            if (yy >= 0 && yy < 512 && xx >= 0 && xx < 512)
                v = g_dec[(((size_t)b * 64 + c0 + dl) * 512 + yy) * 512 + xx];
            tile[dl][r] = v;
        }
        __syncthreads();
#pragma unroll
        for (int dl = 0; dl < 16; dl++) {
            int d = c0 + dl;
            const float* w0 = ws + d * 9;
            const float* w1 = ws + (64 + d) * 9;
            const float* w2 = ws + (128 + d) * 9;
#pragma unroll
            for (int dy = 0; dy < 3; dy++)
#pragma unroll
                for (int dx = 0; dx < 3; dx++) {
                    float v = tile[dl][(py + dy) * 18 + px + dx];
                    int wi = dy * 3 + dx;
                    a0 = fmaf(v, w0[wi], a0);
                    a1 = fmaf(v, w1[wi], a1);
                    a2 = fmaf(v, w2[wi], a2);
                }
        }
    }
    int Y = th * 16 + py, X = tw * 16 + px;
    size_t o = (size_t)b * 3 * 262144 + (size_t)Y * 512 + X;
    out[o]              = 1.f / (1.f + expf(-a0));
    out[o +   262144]   = 1.f / (1.f + expf(-a1));
    out[o + 2*262144]   = 1.f / (1.f + expf(-a2));
}

// ---------------- launch --------------------------------------------------------
extern "C" void kernel_launch(void* const* d_in, const int* in_sizes, int n_in,
                              void* d_out, int out_size) {
    const float* x         = (const float*)d_in[0];
    const float* patch_w   = (const float*)d_in[1];
    const float* patch_b   = (const float*)d_in[2];
    const float* in_proj_w = (const float*)d_in[3];
    const float* conv1d_w  = (const float*)d_in[4];
    const float* conv1d_b  = (const float*)d_in[5];
    const float* x_proj_w  = (const float*)d_in[6];
    const float* dt_proj_w = (const float*)d_in[7];
    const float* dt_proj_b = (const float*)d_in[8];
    const float* A_log     = (const float*)d_in[9];
    const float* Dv        = (const float*)d_in[10];
    const float* out_proj_w= (const float*)d_in[11];
    const float* deconv_w  = (const float*)d_in[12];
    const float* deconv_b  = (const float*)d_in[13];
    const float* dec_conv_w= (const float*)d_in[14];
    const float* dec_conv_b= (const float*)d_in[15];
    float* out = (float*)d_out;

    float *Ape, *seq, *xz, *uact, *dbc, *yg, *gout, *dec;
    cudaGetSymbolAddress((void**)&Ape,  g_Ape);
    cudaGetSymbolAddress((void**)&seq,  g_seq);
    cudaGetSymbolAddress((void**)&xz,   g_xz);
    cudaGetSymbolAddress((void**)&uact, g_uact);
    cudaGetSymbolAddress((void**)&dbc,  g_dbc);
    cudaGetSymbolAddress((void**)&yg,   g_yg);
    cudaGetSymbolAddress((void**)&gout, g_gout);
    cudaGetSymbolAddress((void**)&dec,  g_dec);

    // 1. patch im2col + patch embed GEMM  (seq = Ape @ patch_w^T + patch_b)
    im2col_kernel<<<(ROWS * 768 + 255) / 256, 256>>>(x);
    sgemm_kernel<true, 0><<<dim3(2, 64), 256>>>(Ape, patch_w, patch_b, seq, ROWS, DM, 768);

    // 2. in_proj: xz = seq @ in_proj_w^T
    sgemm_kernel<true, 0><<<dim3(6, 64), 256>>>(seq, in_proj_w, nullptr, xz, ROWS, 2 * DI, DM);

    // 3. depthwise causal conv1d + silu
    conv1d_silu_kernel<<<(ROWS * DI + 255) / 256, 256>>>(conv1d_w, conv1d_b);

    // 4. x_proj: dbc = uact @ x_proj_w^T   (N = 44)
    sgemm_kernel<true, 0><<<dim3(1, 64), 256>>>(uact, x_proj_w, nullptr, dbc, ROWS, DBC_N, DI);

    // 5. dt_proj + softplus
    dtproj_kernel<<<ROWS, DI>>>(dt_proj_w, dt_proj_b);

    // 6. selective scan + gate
    scan_kernel<<<(BATCH * DI) / 16, 256>>>(A_log, Dv);

    // 7. out_proj: gout = yg @ out_proj_w^T
    sgemm_kernel<true, 0><<<dim3(2, 64), 256>>>(yg, out_proj_w, nullptr, gout, ROWS, DM, DI);

    // 8. deconv as GEMM (NN) with relu + scatter epilogue -> g_dec
    sgemm_kernel<false, 1><<<dim3(128, 64), 256>>>(gout, deconv_w, deconv_b, dec, ROWS, 16384, DM);

    // 9. 3x3 conv + bias + sigmoid -> output
    conv3_sigmoid_kernel<<<dim3(32, 32, 8), 256>>>(dec_conv_w, dec_conv_b, out);
}

// round 3
// speedup vs baseline: 1.6288x; 1.6288x over previous
#include <cuda_runtime.h>
#include <cuda_bf16.h>
#include <mma.h>
#include <math.h>
#include <stdint.h>

using namespace nvcuda;

#define BATCH 8
#define LSEQ  1024
#define ROWS  (BATCH*LSEQ)   // 8192
#define DM    192
#define DI    384
#define DS    16
#define DTR   12
#define DBC_N (DTR + 2*DS)   // 44
#define NDEC  16384          // 64*16*16 deconv GEMM N

// ---------------- scratch (static device globals; no runtime alloc) -------------
__device__ float g_Ape [ROWS*768];
__device__ float g_seq [ROWS*DM];
__device__ float g_xz  [ROWS*2*DI];
__device__ float g_uact[ROWS*DI];
__device__ float g_dbc [ROWS*DBC_N];
__device__ float g_delta[ROWS*DI];
__device__ float g_yg  [ROWS*DI];
__device__ float g_gout[ROWS*DM];
__device__ __nv_bfloat16 g_goutb[ROWS*DM];        // bf16 G for tensor GEMM
__device__ __nv_bfloat16 g_wtb [(size_t)NDEC*DM]; // bf16 W^T [16384 x 192]
__device__ float g_dec [(size_t)BATCH*64*512*512];

// ---------------- im2col for 16x16 patch embedding ----------------------------
__global__ void im2col_kernel(const float* __restrict__ x) {
    int gid = blockIdx.x * 256 + threadIdx.x;
    if (gid >= ROWS * 768) return;
    int row = gid / 768, k = gid - row * 768;
    int c = k >> 8, rem = k & 255, p = rem >> 4, q = rem & 15;
    int b = row >> 10, hw = row & 1023, h = hw >> 5, w = hw & 31;
    g_Ape[gid] = x[((b * 3 + c) * 512 + h * 16 + p) * 512 + w * 16 + q];
}

// ---------------- generic 128x128x8 SGEMM, 8x8 per thread (fp32 path) ----------
template<bool BT>
__global__ __launch_bounds__(256)
void sgemm_kernel(const float* __restrict__ A, const float* __restrict__ B,
                  const float* __restrict__ bias, float* __restrict__ C,
                  int M, int N, int K)
{
    __shared__ float As[8][128];
    __shared__ float Bs[8][128];
    int tid = threadIdx.x;
    int bm = blockIdx.y * 128, bn = blockIdx.x * 128;
    int a_r = tid >> 1, a_k = (tid & 1) << 2;
    int ty = tid >> 4, tx = tid & 15;

    float acc[8][8];
#pragma unroll
    for (int i = 0; i < 8; i++)
#pragma unroll
        for (int j = 0; j < 8; j++) acc[i][j] = 0.f;

    for (int k0 = 0; k0 < K; k0 += 8) {
        float4 av = *(const float4*)(A + (size_t)(bm + a_r) * K + k0 + a_k);
        As[a_k + 0][a_r] = av.x; As[a_k + 1][a_r] = av.y;
        As[a_k + 2][a_r] = av.z; As[a_k + 3][a_r] = av.w;
        if (BT) {
            int n = bn + a_r;
            float4 bv = make_float4(0.f, 0.f, 0.f, 0.f);
            if (n < N) bv = *(const float4*)(B + (size_t)n * K + k0 + a_k);
            Bs[a_k + 0][a_r] = bv.x; Bs[a_k + 1][a_r] = bv.y;
            Bs[a_k + 2][a_r] = bv.z; Bs[a_k + 3][a_r] = bv.w;
        } else {
            int kk = tid >> 5, c4 = (tid & 31) << 2;
            int n = bn + c4;
            float4 bv = make_float4(0.f, 0.f, 0.f, 0.f);
            const float* bp = B + (size_t)(k0 + kk) * N + n;
            if (n + 3 < N) bv = *(const float4*)bp;
            else {
                if (n     < N) bv.x = bp[0];
                if (n + 1 < N) bv.y = bp[1];
                if (n + 2 < N) bv.z = bp[2];
            }
            *(float4*)&Bs[kk][c4] = bv;
        }
        __syncthreads();
#pragma unroll
        for (int kk = 0; kk < 8; kk++) {
            float4 a0 = *(const float4*)&As[kk][ty * 8];
            float4 a1 = *(const float4*)&As[kk][ty * 8 + 4];
            float4 b0 = *(const float4*)&Bs[kk][tx * 8];
            float4 b1 = *(const float4*)&Bs[kk][tx * 8 + 4];
            float ra[8] = {a0.x, a0.y, a0.z, a0.w, a1.x, a1.y, a1.z, a1.w};
            float rb[8] = {b0.x, b0.y, b0.z, b0.w, b1.x, b1.y, b1.z, b1.w};
#pragma unroll
            for (int i = 0; i < 8; i++)
#pragma unroll
                for (int j = 0; j < 8; j++)
                    acc[i][j] = fmaf(ra[i], rb[j], acc[i][j]);
        }
        __syncthreads();
    }
#pragma unroll
    for (int i = 0; i < 8; i++) {
        int m = bm + ty * 8 + i;
#pragma unroll
        for (int j = 0; j < 8; j++) {
            int n = bn + tx * 8 + j;
            if (n < N)
                C[(size_t)m * N + n] = acc[i][j] + (bias ? bias[n] : 0.f);
        }
    }
}

// ---------------- depthwise causal conv1d (k=4) + bias + silu -------------------
__global__ void conv1d_silu_kernel(const float* __restrict__ cw, const float* __restrict__ cb) {
    int gid = blockIdx.x * 256 + threadIdx.x;
    if (gid >= ROWS * DI) return;
    int idx = gid / DI, d = gid - idx * DI;
    int l = idx & 1023;
    float s = cb[d];
#pragma unroll
    for (int k = 0; k < 4; k++) {
        int ll = l - 3 + k;
        if (ll >= 0)
            s = fmaf(g_xz[(size_t)(idx - 3 + k) * 768 + d], cw[d * 4 + k], s);
    }
    g_uact[gid] = s / (1.f + expf(-s));
}

// ---------------- dt_proj + softplus -------------------------------------------
__global__ void dtproj_kernel(const float* __restrict__ dpw, const float* __restrict__ dpb) {
    int idx = blockIdx.x;
    int d = threadIdx.x;
    __shared__ float dts[DTR];
    if (d < DTR) dts[d] = g_dbc[idx * DBC_N + d];
    __syncthreads();
    float s = dpb[d];
#pragma unroll
    for (int r = 0; r < DTR; r++) s = fmaf(dts[r], dpw[d * DTR + r], s);
    g_delta[(size_t)idx * DI + d] = fmaxf(s, 0.f) + log1pf(expf(-fabsf(s)));
}

// ---------------- selective scan ------------------------------------------------
__global__ __launch_bounds__(256)
void scan_kernel(const float* __restrict__ A_log, const float* __restrict__ Dv) {
    int tid = threadIdx.x;
    int g = blockIdx.x * 16 + (tid >> 4);
    int lane = tid & 15;
    int b = g / DI, d = g - b * DI;
    float An = -expf(A_log[d * DS + lane]);
    float Dd = Dv[d];
    float h = 0.f;
    int base = b * LSEQ;
    for (int l = 0; l < LSEQ; l++) {
        int idx = base + l;
        float delta = g_delta[(size_t)idx * DI + d];
        float uu    = g_uact [(size_t)idx * DI + d];
        float Bn    = g_dbc[idx * DBC_N + DTR + lane];
        float Cn    = g_dbc[idx * DBC_N + DTR + DS + lane];
        h = fmaf(expf(delta * An), h, delta * Bn * uu);
        float t = h * Cn;
        t += __shfl_xor_sync(0xffffffffu, t, 8);
        t += __shfl_xor_sync(0xffffffffu, t, 4);
        t += __shfl_xor_sync(0xffffffffu, t, 2);
        t += __shfl_xor_sync(0xffffffffu, t, 1);
        if (lane == 0) {
            float z = g_xz[(size_t)idx * 768 + DI + d];
            float y = fmaf(uu, Dd, t);
            g_yg[(size_t)idx * DI + d] = y * (z / (1.f + expf(-z)));
        }
    }
}

// ---------------- converts for tensor-core deconv -------------------------------
__global__ void cvt_g_kernel() {
    int i = blockIdx.x * 256 + threadIdx.x;
    if (i < ROWS * DM) g_goutb[i] = __float2bfloat16(g_gout[i]);
}
__global__ void transpose_w_kernel(const float* __restrict__ W) {
    int i = blockIdx.x * 256 + threadIdx.x;   // over 192*16384, coalesced read
    if (i >= DM * NDEC) return;
    int k = i >> 14, n = i & (NDEC - 1);
    g_wtb[(size_t)n * DM + k] = __float2bfloat16(W[i]);
}

// ---------------- WMMA bf16 deconv GEMM + bias + relu + patch scatter -----------
// D[8192 x 16384] = G[8192 x 192] @ Wt^T ; tile 128x128, K=192 resident in smem.
// 8 warps, each computes 32x64 via 2x4 wmma 16x16x16 fragments.
#define ASTRIDE 200   // 192 + 8 pad (bf16 elements)
#define SSTRIDE 132   // stage row stride (floats)
__global__ __launch_bounds__(256)
void deconv_wmma_kernel(const __nv_bfloat16* __restrict__ G,
                        const __nv_bfloat16* __restrict__ Wt,
                        const float* __restrict__ bias,
                        float* __restrict__ out)
{
    extern __shared__ char smem[];
    __nv_bfloat16* As = (__nv_bfloat16*)smem;          // 128 x ASTRIDE
    __nv_bfloat16* Bs = As + 128 * ASTRIDE;            // 128 x ASTRIDE
    float* stage = (float*)smem;                       // 128 x SSTRIDE (reuses As/Bs)

    int tid = threadIdx.x;
    int bn = blockIdx.x * 128, bm = blockIdx.y * 128;

    // load A (G rows) and B (Wt rows) tiles: 128 rows x 192 bf16 each
    {
        const char* gsrc = (const char*)(G + (size_t)bm * DM);
        const char* wsrc = (const char*)(Wt + (size_t)bn * DM);
#pragma unroll 4
        for (int u = tid; u < 3072; u += 256) {
            int r = u / 24, j = u % 24;          // 24 float4 (=192 bf16) per row
            *(float4*)((char*)As + r * (ASTRIDE * 2) + j * 16) =
                *(const float4*)(gsrc + r * 384 + j * 16);
            *(float4*)((char*)Bs + r * (ASTRIDE * 2) + j * 16) =
                *(const float4*)(wsrc + r * 384 + j * 16);
        }
    }
    __syncthreads();

    int wid = tid >> 5;
    int wm = (wid >> 1) * 32;      // warp row offset (4 warps down)
    int wn = (wid & 1) * 64;       // warp col offset (2 warps across)

    wmma::fragment<wmma::accumulator, 16, 16, 16, float> acc[2][4];
#pragma unroll
    for (int i = 0; i < 2; i++)
#pragma unroll
        for (int j = 0; j < 4; j++) wmma::fill_fragment(acc[i][j], 0.f);

#pragma unroll
    for (int k = 0; k < DM; k += 16) {
        wmma::fragment<wmma::matrix_a, 16, 16, 16, __nv_bfloat16, wmma::row_major> af[2];
        wmma::fragment<wmma::matrix_b, 16, 16, 16, __nv_bfloat16, wmma::col_major> bf[4];
#pragma unroll
        for (int i = 0; i < 2; i++)
            wmma::load_matrix_sync(af[i], As + (wm + i * 16) * ASTRIDE + k, ASTRIDE);
#pragma unroll
        for (int j = 0; j < 4; j++)
            wmma::load_matrix_sync(bf[j], Bs + (wn + j * 16) * ASTRIDE + k, ASTRIDE);
#pragma unroll
        for (int i = 0; i < 2; i++)
#pragma unroll
            for (int j = 0; j < 4; j++)
                wmma::mma_sync(acc[i][j], af[i], bf[j], acc[i][j]);
    }
    __syncthreads();   // done reading As/Bs; stage aliases them

#pragma unroll
    for (int i = 0; i < 2; i++)
#pragma unroll
        for (int j = 0; j < 4; j++)
            wmma::store_matrix_sync(stage + (wm + i * 16) * SSTRIDE + wn + j * 16,
                                    acc[i][j], SSTRIDE, wmma::mem_row_major);
    __syncthreads();

    // bias + relu + coalesced patch scatter: 32 contiguous 2KB output rows.
    // tile rows m_local = h*32 + w (h in 0..3); tile cols n_local = p*16 + q (p in 0..7)
    {
        int b_img  = bm >> 10;
        int h_base = (bm & 1023) >> 5;
        int dch    = bn >> 8;
        int p_base = (bn >> 4) & 15;
        float bv = bias[dch];
        float* dst = out + (size_t)b_img * 16777216 + (size_t)dch * 262144;
#pragma unroll 4
        for (int i = tid; i < 4096; i += 256) {
            int row = i >> 7;                  // 0..31 = h*8 + p
            int c4  = (i & 127) * 4;           // output column (w*16 + q), q%4==0
            int h = row >> 3, p = row & 7;
            int w = c4 >> 4, q = c4 & 15;
            float4 v = *(float4*)(stage + (h * 32 + w) * SSTRIDE + p * 16 + q);
            v.x = fmaxf(v.x + bv, 0.f); v.y = fmaxf(v.y + bv, 0.f);
            v.z = fmaxf(v.z + bv, 0.f); v.w = fmaxf(v.w + bv, 0.f);
            *(float4*)(dst + (size_t)((h_base + h) * 16 + p_base + p) * 512 + c4) = v;
        }
    }
}

// ---------------- 3x3 conv (64->3, pad 1) + bias + sigmoid ---------------------
__global__ __launch_bounds__(256)
void conv3_sigmoid_kernel(const float* __restrict__ W, const float* __restrict__ wb,
                          float* __restrict__ out) {
    __shared__ float ws[3 * 64 * 9];
    __shared__ float tile[16][324];
    int b = blockIdx.z, th = blockIdx.y, tw = blockIdx.x;
    int tid = threadIdx.x;
    for (int i = tid; i < 1728; i += 256) ws[i] = W[i];
    int py = tid >> 4, px = tid & 15;
    float a0 = wb[0], a1 = wb[1], a2 = wb[2];
    int y0 = th * 16 - 1, x0 = tw * 16 - 1;

    for (int c0 = 0; c0 < 64; c0 += 16) {
        __syncthreads();
        for (int i = tid; i < 16 * 324; i += 256) {
            int dl = i / 324, r = i - dl * 324;
            int yy = y0 + r / 18, xx = x0 + (r % 18);
            float v = 0.f;
            if (yy >= 0 && yy < 512 && xx >= 0 && xx < 512)
                v = g_dec[(((size_t)b * 64 + c0 + dl) * 512 + yy) * 512 + xx];
            tile[dl][r] = v;
        }
        __syncthreads();
#pragma unroll
        for (int dl = 0; dl < 16; dl++) {
            int d = c0 + dl;
            const float* w0 = ws + d * 9;
            const float* w1 = ws + (64 + d) * 9;
            const float* w2 = ws + (128 + d) * 9;
#pragma unroll
            for (int dy = 0; dy < 3; dy++)
#pragma unroll
                for (int dx = 0; dx < 3; dx++) {
                    float v = tile[dl][(py + dy) * 18 + px + dx];
                    int wi = dy * 3 + dx;
                    a0 = fmaf(v, w0[wi], a0);
                    a1 = fmaf(v, w1[wi], a1);
                    a2 = fmaf(v, w2[wi], a2);
                }
        }
    }
    int Y = th * 16 + py, X = tw * 16 + px;
    size_t o = (size_t)b * 3 * 262144 + (size_t)Y * 512 + X;
    out[o]              = 1.f / (1.f + expf(-a0));
    out[o +   262144]   = 1.f / (1.f + expf(-a1));
    out[o + 2*262144]   = 1.f / (1.f + expf(-a2));
}

// ---------------- launch --------------------------------------------------------
extern "C" void kernel_launch(void* const* d_in, const int* in_sizes, int n_in,
                              void* d_out, int out_size) {
    const float* x         = (const float*)d_in[0];
    const float* patch_w   = (const float*)d_in[1];
    const float* patch_b   = (const float*)d_in[2];
    const float* in_proj_w = (const float*)d_in[3];
    const float* conv1d_w  = (const float*)d_in[4];
    const float* conv1d_b  = (const float*)d_in[5];
    const float* x_proj_w  = (const float*)d_in[6];
    const float* dt_proj_w = (const float*)d_in[7];
    const float* dt_proj_b = (const float*)d_in[8];
    const float* A_log     = (const float*)d_in[9];
    const float* Dv        = (const float*)d_in[10];
    const float* out_proj_w= (const float*)d_in[11];
    const float* deconv_w  = (const float*)d_in[12];
    const float* deconv_b  = (const float*)d_in[13];
    const float* dec_conv_w= (const float*)d_in[14];
    const float* dec_conv_b= (const float*)d_in[15];
    float* out = (float*)d_out;

    float *Ape, *seq, *xz, *uact, *dbc, *yg, *gout, *dec;
    __nv_bfloat16 *goutb, *wtb;
    cudaGetSymbolAddress((void**)&Ape,  g_Ape);
    cudaGetSymbolAddress((void**)&seq,  g_seq);
    cudaGetSymbolAddress((void**)&xz,   g_xz);
    cudaGetSymbolAddress((void**)&uact, g_uact);
    cudaGetSymbolAddress((void**)&dbc,  g_dbc);
    cudaGetSymbolAddress((void**)&yg,   g_yg);
    cudaGetSymbolAddress((void**)&gout, g_gout);
    cudaGetSymbolAddress((void**)&goutb,g_goutb);
    cudaGetSymbolAddress((void**)&wtb,  g_wtb);
    cudaGetSymbolAddress((void**)&dec,  g_dec);

    const int DSMEM = 2 * 128 * ASTRIDE * 2;   // 102400 bytes
    cudaFuncSetAttribute(deconv_wmma_kernel,
                         cudaFuncAttributeMaxDynamicSharedMemorySize, DSMEM);

    // 1. patch embed
    im2col_kernel<<<(ROWS * 768 + 255) / 256, 256>>>(x);
    sgemm_kernel<true><<<dim3(2, 64), 256>>>(Ape, patch_w, patch_b, seq, ROWS, DM, 768);
    // 2. in_proj
    sgemm_kernel<true><<<dim3(6, 64), 256>>>(seq, in_proj_w, nullptr, xz, ROWS, 2 * DI, DM);
    // 3. conv1d + silu
    conv1d_silu_kernel<<<(ROWS * DI + 255) / 256, 256>>>(conv1d_w, conv1d_b);
    // 4. x_proj
    sgemm_kernel<true><<<dim3(1, 64), 256>>>(uact, x_proj_w, nullptr, dbc, ROWS, DBC_N, DI);
    // 5. dt_proj + softplus
    dtproj_kernel<<<ROWS, DI>>>(dt_proj_w, dt_proj_b);
    // 6. selective scan + gate
    scan_kernel<<<(BATCH * DI) / 16, 256>>>(A_log, Dv);
    // 7. out_proj
    sgemm_kernel<true><<<dim3(2, 64), 256>>>(yg, out_proj_w, nullptr, gout, ROWS, DM, DI);
    // 8. deconv on tensor cores (WMMA bf16 -> compiles for compute_103)
    cvt_g_kernel<<<(ROWS * DM + 255) / 256, 256>>>();
    transpose_w_kernel<<<(DM * NDEC + 255) / 256, 256>>>(deconv_w);
    deconv_wmma_kernel<<<dim3(128, 64), 256, DSMEM>>>(goutb, wtb, deconv_b, dec);
    // 9. 3x3 conv + sigmoid
    conv3_sigmoid_kernel<<<dim3(32, 32, 8), 256>>>(dec_conv_w, dec_conv_b, out);
}

// round 4
// speedup vs baseline: 2.0208x; 1.2407x over previous
#include <cuda_runtime.h>
#include <cuda_bf16.h>
#include <mma.h>
#include <math.h>
#include <stdint.h>

using namespace nvcuda;

#define BATCH 8
#define LSEQ  1024
#define ROWS  (BATCH*LSEQ)   // 8192
#define DM    192
#define DI    384
#define DS    16
#define DTR   12
#define DBC_N (DTR + 2*DS)   // 44
#define NDEC  16384

typedef __nv_bfloat16 bf16;

// ---------------- scratch -------------------------------------------------------
__device__ bf16  g_Apeb[ROWS*768];
__device__ bf16  g_seqb[ROWS*DM];
__device__ float g_xz  [ROWS*2*DI];
__device__ float g_uact[ROWS*DI];
__device__ bf16  g_uactb[ROWS*DI];
__device__ float g_dbc [ROWS*DBC_N];
__device__ float g_delta[ROWS*DI];
__device__ bf16  g_ygb [ROWS*DI];
__device__ bf16  g_goutb[ROWS*DM];
__device__ bf16  g_wtb [(size_t)NDEC*DM];
__device__ bf16  g_decb[(size_t)BATCH*64*512*512];   // 268 MB
// weight bf16 copies
__device__ bf16  g_pwb [DM*768];
__device__ bf16  g_ipwb[2*DI*DM];
__device__ bf16  g_xpwb[DBC_N*DI];
__device__ bf16  g_opwb[DM*DI];

// ---------------- generic float -> bf16 convert ---------------------------------
__global__ void cvt_kernel(const float* __restrict__ s, bf16* __restrict__ d, int n) {
    int i = blockIdx.x * 256 + threadIdx.x;
    if (i < n) d[i] = __float2bfloat16(s[i]);
}
__global__ void transpose_w_kernel(const float* __restrict__ W) {
    int i = blockIdx.x * 256 + threadIdx.x;
    if (i >= DM * NDEC) return;
    int n = i / DM, k = i - n * DM;                  // write coalesced
    g_wtb[(size_t)n * DM + k] = __float2bfloat16(W[(size_t)k * NDEC + n]);
}

// ---------------- im2col (writes bf16) ------------------------------------------
__global__ void im2col_kernel(const float* __restrict__ x) {
    int gid = blockIdx.x * 256 + threadIdx.x;
    if (gid >= ROWS * 768) return;
    int row = gid / 768, k = gid - row * 768;
    int c = k >> 8, rem = k & 255, p = rem >> 4, q = rem & 15;
    int b = row >> 10, hw = row & 1023, h = hw >> 5, w = hw & 31;
    g_Apeb[gid] = __float2bfloat16(x[((b * 3 + c) * 512 + h * 16 + p) * 512 + w * 16 + q]);
}

// ---------------- generic WMMA bf16 NT GEMM -------------------------------------
// C[M x N] = A[M x K] @ B[N x K]^T ; tile 128x64, K-chunk 64, 8 warps (4x2), fp32 acc.
// OUT_BF16: write bf16, else fp32. bias (fp32, per-col) optional (nullptr).
#define AST 72
#define CST 68
template<bool OUT_BF16>
__global__ __launch_bounds__(256)
void wgemm_kernel(const bf16* __restrict__ A, const bf16* __restrict__ B,
                  const float* __restrict__ bias, void* __restrict__ Cout,
                  int N, int K)
{
    __shared__ __align__(16) char sm[34816];
    bf16* As = (bf16*)sm;                 // 128 x AST
    bf16* Bs = As + 128 * AST;            // 64 x AST
    float* stage = (float*)sm;            // 128 x CST

    int tid = threadIdx.x;
    int bm = blockIdx.y * 128, bn = blockIdx.x * 64;
    int wid = tid >> 5;
    int wm = (wid >> 1) * 32, wn = (wid & 1) * 32;

    wmma::fragment<wmma::accumulator, 16, 16, 16, float> acc[2][2];
#pragma unroll
    for (int i = 0; i < 2; i++)
#pragma unroll
        for (int j = 0; j < 2; j++) wmma::fill_fragment(acc[i][j], 0.f);

    for (int k0 = 0; k0 < K; k0 += 64) {
        // A tile: 128 rows x 64 bf16 (8 float4/row)
#pragma unroll 4
        for (int u = tid; u < 1024; u += 256) {
            int r = u >> 3, j = u & 7;
            *(float4*)((char*)As + r * (AST * 2) + j * 16) =
                *(const float4*)(A + (size_t)(bm + r) * K + k0 + j * 8);
        }
        // B tile: 64 rows x 64 bf16 (guard rows >= N)
#pragma unroll 2
        for (int u = tid; u < 512; u += 256) {
            int r = u >> 3, j = u & 7;
            float4 v = make_float4(0.f, 0.f, 0.f, 0.f);
            if (bn + r < N)
                v = *(const float4*)(B + (size_t)(bn + r) * K + k0 + j * 8);
            *(float4*)((char*)Bs + r * (AST * 2) + j * 16) = v;
        }
        __syncthreads();
#pragma unroll
        for (int kk = 0; kk < 4; kk++) {
            wmma::fragment<wmma::matrix_a, 16, 16, 16, bf16, wmma::row_major> af[2];
            wmma::fragment<wmma::matrix_b, 16, 16, 16, bf16, wmma::col_major> bf_[2];
#pragma unroll
            for (int i = 0; i < 2; i++)
                wmma::load_matrix_sync(af[i], As + (wm + i * 16) * AST + kk * 16, AST);
#pragma unroll
            for (int j = 0; j < 2; j++)
                wmma::load_matrix_sync(bf_[j], Bs + (wn + j * 16) * AST + kk * 16, AST);
#pragma unroll
            for (int i = 0; i < 2; i++)
#pragma unroll
                for (int j = 0; j < 2; j++)
                    wmma::mma_sync(acc[i][j], af[i], bf_[j], acc[i][j]);
        }
        __syncthreads();
    }

#pragma unroll
    for (int i = 0; i < 2; i++)
#pragma unroll
        for (int j = 0; j < 2; j++)
            wmma::store_matrix_sync(stage + (wm + i * 16) * CST + wn + j * 16,
                                    acc[i][j], CST, wmma::mem_row_major);
    __syncthreads();

#pragma unroll 4
    for (int u = tid; u < 8192; u += 256) {
        int r = u >> 6, c = u & 63;
        int n = bn + c;
        if (n >= N) continue;
        float v = stage[r * CST + c] + (bias ? bias[n] : 0.f);
        if (OUT_BF16) ((bf16*)Cout)[(size_t)(bm + r) * N + n] = __float2bfloat16(v);
        else          ((float*)Cout)[(size_t)(bm + r) * N + n] = v;
    }
}

// ---------------- depthwise causal conv1d + silu (fp32 + bf16 outs) -------------
__global__ void conv1d_silu_kernel(const float* __restrict__ cw, const float* __restrict__ cb) {
    int gid = blockIdx.x * 256 + threadIdx.x;
    if (gid >= ROWS * DI) return;
    int idx = gid / DI, d = gid - idx * DI;
    int l = idx & 1023;
    float s = cb[d];
#pragma unroll
    for (int k = 0; k < 4; k++) {
        int ll = l - 3 + k;
        if (ll >= 0)
            s = fmaf(g_xz[(size_t)(idx - 3 + k) * 768 + d], cw[d * 4 + k], s);
    }
    float r = s / (1.f + expf(-s));
    g_uact[gid] = r;
    g_uactb[gid] = __float2bfloat16(r);
}

// ---------------- dt_proj + softplus -------------------------------------------
__global__ void dtproj_kernel(const float* __restrict__ dpw, const float* __restrict__ dpb) {
    int idx = blockIdx.x;
    int d = threadIdx.x;
    __shared__ float dts[DTR];
    if (d < DTR) dts[d] = g_dbc[idx * DBC_N + d];
    __syncthreads();
    float s = dpb[d];
#pragma unroll
    for (int r = 0; r < DTR; r++) s = fmaf(dts[r], dpw[d * DTR + r], s);
    g_delta[(size_t)idx * DI + d] = fmaxf(s, 0.f) + log1pf(expf(-fabsf(s)));
}

// ---------------- selective scan (writes bf16) ----------------------------------
__global__ __launch_bounds__(256)
void scan_kernel(const float* __restrict__ A_log, const float* __restrict__ Dv) {
    int tid = threadIdx.x;
    int g = blockIdx.x * 16 + (tid >> 4);
    int lane = tid & 15;
    int b = g / DI, d = g - b * DI;
    float An = -expf(A_log[d * DS + lane]);
    float Dd = Dv[d];
    float h = 0.f;
    int base = b * LSEQ;
    for (int l = 0; l < LSEQ; l++) {
        int idx = base + l;
        float delta = g_delta[(size_t)idx * DI + d];
        float uu    = g_uact [(size_t)idx * DI + d];
        float Bn    = g_dbc[idx * DBC_N + DTR + lane];
        float Cn    = g_dbc[idx * DBC_N + DTR + DS + lane];
        h = fmaf(expf(delta * An), h, delta * Bn * uu);
        float t = h * Cn;
        t += __shfl_xor_sync(0xffffffffu, t, 8);
        t += __shfl_xor_sync(0xffffffffu, t, 4);
        t += __shfl_xor_sync(0xffffffffu, t, 2);
        t += __shfl_xor_sync(0xffffffffu, t, 1);
        if (lane == 0) {
            float z = g_xz[(size_t)idx * 768 + DI + d];
            float y = fmaf(uu, Dd, t);
            g_ygb[(size_t)idx * DI + d] = __float2bfloat16(y * (z / (1.f + expf(-z))));
        }
    }
}

// ---------------- WMMA bf16 deconv GEMM + bias + relu + bf16 patch scatter ------
#define ASTRIDE 200
#define SSTRIDE 132
__global__ __launch_bounds__(256)
void deconv_wmma_kernel(const bf16* __restrict__ G, const bf16* __restrict__ Wt,
                        const float* __restrict__ bias, bf16* __restrict__ out)
{
    extern __shared__ char smem[];
    bf16* As = (bf16*)smem;
    bf16* Bs = As + 128 * ASTRIDE;
    float* stage = (float*)smem;

    int tid = threadIdx.x;
    int bn = blockIdx.x * 128, bm = blockIdx.y * 128;

    {
        const char* gsrc = (const char*)(G + (size_t)bm * DM);
        const char* wsrc = (const char*)(Wt + (size_t)bn * DM);
#pragma unroll 4
        for (int u = tid; u < 3072; u += 256) {
            int r = u / 24, j = u % 24;
            *(float4*)((char*)As + r * (ASTRIDE * 2) + j * 16) =
                *(const float4*)(gsrc + r * 384 + j * 16);
            *(float4*)((char*)Bs + r * (ASTRIDE * 2) + j * 16) =
                *(const float4*)(wsrc + r * 384 + j * 16);
        }
    }
    __syncthreads();

    int wid = tid >> 5;
    int wm = (wid >> 1) * 32, wn = (wid & 1) * 64;

    wmma::fragment<wmma::accumulator, 16, 16, 16, float> acc[2][4];
#pragma unroll
    for (int i = 0; i < 2; i++)
#pragma unroll
        for (int j = 0; j < 4; j++) wmma::fill_fragment(acc[i][j], 0.f);

#pragma unroll
    for (int k = 0; k < DM; k += 16) {
        wmma::fragment<wmma::matrix_a, 16, 16, 16, bf16, wmma::row_major> af[2];
        wmma::fragment<wmma::matrix_b, 16, 16, 16, bf16, wmma::col_major> bf_[4];
#pragma unroll
        for (int i = 0; i < 2; i++)
            wmma::load_matrix_sync(af[i], As + (wm + i * 16) * ASTRIDE + k, ASTRIDE);
#pragma unroll
        for (int j = 0; j < 4; j++)
            wmma::load_matrix_sync(bf_[j], Bs + (wn + j * 16) * ASTRIDE + k, ASTRIDE);
#pragma unroll
        for (int i = 0; i < 2; i++)
#pragma unroll
            for (int j = 0; j < 4; j++)
                wmma::mma_sync(acc[i][j], af[i], bf_[j], acc[i][j]);
    }
    __syncthreads();

#pragma unroll
    for (int i = 0; i < 2; i++)
#pragma unroll
        for (int j = 0; j < 4; j++)
            wmma::store_matrix_sync(stage + (wm + i * 16) * SSTRIDE + wn + j * 16,
                                    acc[i][j], SSTRIDE, wmma::mem_row_major);
    __syncthreads();

    // bias + relu + bf16 pack + coalesced patch scatter (32 contiguous 1KB rows)
    {
        int b_img  = bm >> 10;
        int h_base = (bm & 1023) >> 5;
        int dch    = bn >> 8;
        int p_base = (bn >> 4) & 15;
        float bv = bias[dch];
        bf16* dst = out + (size_t)b_img * 16777216 + (size_t)dch * 262144;
#pragma unroll 4
        for (int i = tid; i < 2048; i += 256) {
            int row = i >> 6;                 // 0..31 = h*8 + p
            int c8  = (i & 63) * 8;           // output col (w*16+q), 8 at a time
            int h = row >> 3, p = row & 7;
            int w = c8 >> 4, q = c8 & 15;
            const float* sp = stage + (h * 32 + w) * SSTRIDE + p * 16 + q;
            float4 v0 = *(const float4*)sp;
            float4 v1 = *(const float4*)(sp + 4);
            __nv_bfloat162 o0 = __floats2bfloat162_rn(fmaxf(v0.x + bv, 0.f), fmaxf(v0.y + bv, 0.f));
            __nv_bfloat162 o1 = __floats2bfloat162_rn(fmaxf(v0.z + bv, 0.f), fmaxf(v0.w + bv, 0.f));
            __nv_bfloat162 o2 = __floats2bfloat162_rn(fmaxf(v1.x + bv, 0.f), fmaxf(v1.y + bv, 0.f));
            __nv_bfloat162 o3 = __floats2bfloat162_rn(fmaxf(v1.z + bv, 0.f), fmaxf(v1.w + bv, 0.f));
            uint4 pk;
            pk.x = *(uint32_t*)&o0; pk.y = *(uint32_t*)&o1;
            pk.z = *(uint32_t*)&o2; pk.w = *(uint32_t*)&o3;
            *(uint4*)(dst + (size_t)((h_base + h) * 16 + p_base + p) * 512 + c8) = pk;
        }
    }
}

// ---------------- 3x3 conv (64->3, pad 1) + bias + sigmoid (bf16 in) ------------
__global__ __launch_bounds__(256)
void conv3_sigmoid_kernel(const float* __restrict__ W, const float* __restrict__ wb,
                          float* __restrict__ out) {
    __shared__ float ws[3 * 64 * 9];
    __shared__ float tile[16][324];
    int b = blockIdx.z, th = blockIdx.y, tw = blockIdx.x;
    int tid = threadIdx.x;
    for (int i = tid; i < 1728; i += 256) ws[i] = W[i];
    int py = tid >> 4, px = tid & 15;
    float a0 = wb[0], a1 = wb[1], a2 = wb[2];
    int y0 = th * 16 - 1, x0 = tw * 16 - 1;

    for (int c0 = 0; c0 < 64; c0 += 16) {
        __syncthreads();
        for (int i = tid; i < 16 * 324; i += 256) {
            int dl = i / 324, r = i - dl * 324;
            int yy = y0 + r / 18, xx = x0 + (r % 18);
            float v = 0.f;
            if (yy >= 0 && yy < 512 && xx >= 0 && xx < 512)
                v = __bfloat162float(g_decb[(((size_t)b * 64 + c0 + dl) * 512 + yy) * 512 + xx]);
            tile[dl][r] = v;
        }
        __syncthreads();
#pragma unroll
        for (int dl = 0; dl < 16; dl++) {
            int d = c0 + dl;
            const float* w0 = ws + d * 9;
            const float* w1 = ws + (64 + d) * 9;
            const float* w2 = ws + (128 + d) * 9;
#pragma unroll
            for (int dy = 0; dy < 3; dy++)
#pragma unroll
                for (int dx = 0; dx < 3; dx++) {
                    float v = tile[dl][(py + dy) * 18 + px + dx];
                    int wi = dy * 3 + dx;
                    a0 = fmaf(v, w0[wi], a0);
                    a1 = fmaf(v, w1[wi], a1);
                    a2 = fmaf(v, w2[wi], a2);
                }
        }
    }
    int Y = th * 16 + py, X = tw * 16 + px;
    size_t o = (size_t)b * 3 * 262144 + (size_t)Y * 512 + X;
    out[o]              = 1.f / (1.f + expf(-a0));
    out[o +   262144]   = 1.f / (1.f + expf(-a1));
    out[o + 2*262144]   = 1.f / (1.f + expf(-a2));
}

// ---------------- launch --------------------------------------------------------
extern "C" void kernel_launch(void* const* d_in, const int* in_sizes, int n_in,
                              void* d_out, int out_size) {
    const float* x         = (const float*)d_in[0];
    const float* patch_w   = (const float*)d_in[1];
    const float* patch_b   = (const float*)d_in[2];
    const float* in_proj_w = (const float*)d_in[3];
    const float* conv1d_w  = (const float*)d_in[4];
    const float* conv1d_b  = (const float*)d_in[5];
    const float* x_proj_w  = (const float*)d_in[6];
    const float* dt_proj_w = (const float*)d_in[7];
    const float* dt_proj_b = (const float*)d_in[8];
    const float* A_log     = (const float*)d_in[9];
    const float* Dv        = (const float*)d_in[10];
    const float* out_proj_w= (const float*)d_in[11];
    const float* deconv_w  = (const float*)d_in[12];
    const float* deconv_b  = (const float*)d_in[13];
    const float* dec_conv_w= (const float*)d_in[14];
    const float* dec_conv_b= (const float*)d_in[15];
    float* out = (float*)d_out;

    bf16 *Apeb, *seqb, *uactb, *ygb, *goutb, *wtb, *decb, *pwb, *ipwb, *xpwb, *opwb;
    float *xz, *uact, *dbc, *delta;
    cudaGetSymbolAddress((void**)&Apeb, g_Apeb);
    cudaGetSymbolAddress((void**)&seqb, g_seqb);
    cudaGetSymbolAddress((void**)&xz,   g_xz);
    cudaGetSymbolAddress((void**)&uact, g_uact);
    cudaGetSymbolAddress((void**)&uactb,g_uactb);
    cudaGetSymbolAddress((void**)&dbc,  g_dbc);
    cudaGetSymbolAddress((void**)&delta,g_delta);
    cudaGetSymbolAddress((void**)&ygb,  g_ygb);
    cudaGetSymbolAddress((void**)&goutb,g_goutb);
    cudaGetSymbolAddress((void**)&wtb,  g_wtb);
    cudaGetSymbolAddress((void**)&decb, g_decb);
    cudaGetSymbolAddress((void**)&pwb,  g_pwb);
    cudaGetSymbolAddress((void**)&ipwb, g_ipwb);
    cudaGetSymbolAddress((void**)&xpwb, g_xpwb);
    cudaGetSymbolAddress((void**)&opwb, g_opwb);

    const int DSMEM = 2 * 128 * ASTRIDE * 2;
    cudaFuncSetAttribute(deconv_wmma_kernel,
                         cudaFuncAttributeMaxDynamicSharedMemorySize, DSMEM);

    // weight converts (tiny)
    cvt_kernel<<<(DM*768 + 255)/256, 256>>>(patch_w, pwb, DM*768);
    cvt_kernel<<<(2*DI*DM + 255)/256, 256>>>(in_proj_w, ipwb, 2*DI*DM);
    cvt_kernel<<<(DBC_N*DI + 255)/256, 256>>>(x_proj_w, xpwb, DBC_N*DI);
    cvt_kernel<<<(DM*DI + 255)/256, 256>>>(out_proj_w, opwb, DM*DI);
    transpose_w_kernel<<<(DM * NDEC + 255) / 256, 256>>>(deconv_w);

    // 1. patch embed (bf16 out)
    im2col_kernel<<<(ROWS * 768 + 255) / 256, 256>>>(x);
    wgemm_kernel<true><<<dim3(3, 64), 256>>>(Apeb, pwb, patch_b, seqb, DM, 768);
    // 2. in_proj (fp32 out)
    wgemm_kernel<false><<<dim3(12, 64), 256>>>(seqb, ipwb, nullptr, xz, 2 * DI, DM);
    // 3. conv1d + silu
    conv1d_silu_kernel<<<(ROWS * DI + 255) / 256, 256>>>(conv1d_w, conv1d_b);
    // 4. x_proj (fp32 out, N=44)
    wgemm_kernel<false><<<dim3(1, 64), 256>>>(uactb, xpwb, nullptr, dbc, DBC_N, DI);
    // 5. dt_proj + softplus
    dtproj_kernel<<<ROWS, DI>>>(dt_proj_w, dt_proj_b);
    // 6. selective scan + gate (bf16 out)
    scan_kernel<<<(BATCH * DI) / 16, 256>>>(A_log, Dv);
    // 7. out_proj (bf16 out -> feeds deconv directly)
    wgemm_kernel<true><<<dim3(3, 64), 256>>>(ygb, opwb, nullptr, goutb, DM, DI);
    // 8. deconv on tensor cores, bf16 output
    deconv_wmma_kernel<<<dim3(128, 64), 256, DSMEM>>>(goutb, wtb, deconv_b, decb);
    // 9. 3x3 conv + sigmoid
    conv3_sigmoid_kernel<<<dim3(32, 32, 8), 256>>>(dec_conv_w, dec_conv_b, out);
}

// round 5
// speedup vs baseline: 2.3425x; 1.1592x over previous
#include <cuda_runtime.h>
#include <cuda_bf16.h>
#include <mma.h>
#include <math.h>
#include <stdint.h>

using namespace nvcuda;

#define BATCH 8
#define LSEQ  1024
#define ROWS  (BATCH*LSEQ)   // 8192
#define DM    192
#define DI    384
#define DS    16
#define DTR   12
#define DBC_N (DTR + 2*DS)   // 44
#define NDEC  16384

typedef __nv_bfloat16 bf16;
typedef unsigned long long u64;

// ---------------- scratch -------------------------------------------------------
__device__ bf16  g_Apeb[ROWS*768];
__device__ bf16  g_seqb[ROWS*DM];
__device__ float g_xz  [ROWS*2*DI];
__device__ float g_uact[ROWS*DI];
__device__ bf16  g_uactb[ROWS*DI];
__device__ float g_dbc [ROWS*DBC_N];
__device__ float g_delta[ROWS*DI];
__device__ bf16  g_ygb [ROWS*DI];
__device__ bf16  g_goutb[ROWS*DM];
__device__ bf16  g_wtb [(size_t)NDEC*DM];
__device__ bf16  g_decb[(size_t)BATCH*64*512*512];   // 268 MB
__device__ bf16  g_pwb [DM*768];
__device__ bf16  g_ipwb[2*DI*DM];
__device__ bf16  g_xpwb[DBC_N*DI];
__device__ bf16  g_opwb[DM*DI];

// ---------------- packed f32x2 helpers ------------------------------------------
__device__ __forceinline__ u64 pk2(float lo, float hi) {
    u64 r; asm("mov.b64 %0, {%1, %2};" : "=l"(r) : "f"(lo), "f"(hi)); return r;
}
__device__ __forceinline__ void unpk2(float& lo, float& hi, u64 v) {
    asm("mov.b64 {%0, %1}, %2;" : "=f"(lo), "=f"(hi) : "l"(v));
}
__device__ __forceinline__ void fma2(u64& acc, u64 a, u64 b) {
    asm("fma.rn.f32x2 %0, %1, %2, %0;" : "+l"(acc) : "l"(a), "l"(b));
}

// ---------------- generic float -> bf16 convert ---------------------------------
__global__ void cvt_kernel(const float* __restrict__ s, bf16* __restrict__ d, int n) {
    int i = blockIdx.x * 256 + threadIdx.x;
    if (i < n) d[i] = __float2bfloat16(s[i]);
}
__global__ void transpose_w_kernel(const float* __restrict__ W) {
    int i = blockIdx.x * 256 + threadIdx.x;
    if (i >= DM * NDEC) return;
    int n = i / DM, k = i - n * DM;
    g_wtb[(size_t)n * DM + k] = __float2bfloat16(W[(size_t)k * NDEC + n]);
}

// ---------------- im2col (writes bf16) ------------------------------------------
__global__ void im2col_kernel(const float* __restrict__ x) {
    int gid = blockIdx.x * 256 + threadIdx.x;
    if (gid >= ROWS * 768) return;
    int row = gid / 768, k = gid - row * 768;
    int c = k >> 8, rem = k & 255, p = rem >> 4, q = rem & 15;
    int b = row >> 10, hw = row & 1023, h = hw >> 5, w = hw & 31;
    g_Apeb[gid] = __float2bfloat16(x[((b * 3 + c) * 512 + h * 16 + p) * 512 + w * 16 + q]);
}

// ---------------- generic WMMA bf16 NT GEMM -------------------------------------
#define AST 72
#define CST 68
template<bool OUT_BF16>
__global__ __launch_bounds__(256)
void wgemm_kernel(const bf16* __restrict__ A, const bf16* __restrict__ B,
                  const float* __restrict__ bias, void* __restrict__ Cout,
                  int N, int K)
{
    __shared__ __align__(16) char sm[34816];
    bf16* As = (bf16*)sm;
    bf16* Bs = As + 128 * AST;
    float* stage = (float*)sm;

    int tid = threadIdx.x;
    int bm = blockIdx.y * 128, bn = blockIdx.x * 64;
    int wid = tid >> 5;
    int wm = (wid >> 1) * 32, wn = (wid & 1) * 32;

    wmma::fragment<wmma::accumulator, 16, 16, 16, float> acc[2][2];
#pragma unroll
    for (int i = 0; i < 2; i++)
#pragma unroll
        for (int j = 0; j < 2; j++) wmma::fill_fragment(acc[i][j], 0.f);

    for (int k0 = 0; k0 < K; k0 += 64) {
#pragma unroll 4
        for (int u = tid; u < 1024; u += 256) {
            int r = u >> 3, j = u & 7;
            *(float4*)((char*)As + r * (AST * 2) + j * 16) =
                *(const float4*)(A + (size_t)(bm + r) * K + k0 + j * 8);
        }
#pragma unroll 2
        for (int u = tid; u < 512; u += 256) {
            int r = u >> 3, j = u & 7;
            float4 v = make_float4(0.f, 0.f, 0.f, 0.f);
            if (bn + r < N)
                v = *(const float4*)(B + (size_t)(bn + r) * K + k0 + j * 8);
            *(float4*)((char*)Bs + r * (AST * 2) + j * 16) = v;
        }
        __syncthreads();
#pragma unroll
        for (int kk = 0; kk < 4; kk++) {
            wmma::fragment<wmma::matrix_a, 16, 16, 16, bf16, wmma::row_major> af[2];
            wmma::fragment<wmma::matrix_b, 16, 16, 16, bf16, wmma::col_major> bf_[2];
#pragma unroll
            for (int i = 0; i < 2; i++)
                wmma::load_matrix_sync(af[i], As + (wm + i * 16) * AST + kk * 16, AST);
#pragma unroll
            for (int j = 0; j < 2; j++)
                wmma::load_matrix_sync(bf_[j], Bs + (wn + j * 16) * AST + kk * 16, AST);
#pragma unroll
            for (int i = 0; i < 2; i++)
#pragma unroll
                for (int j = 0; j < 2; j++)
                    wmma::mma_sync(acc[i][j], af[i], bf_[j], acc[i][j]);
        }
        __syncthreads();
    }

#pragma unroll
    for (int i = 0; i < 2; i++)
#pragma unroll
        for (int j = 0; j < 2; j++)
            wmma::store_matrix_sync(stage + (wm + i * 16) * CST + wn + j * 16,
                                    acc[i][j], CST, wmma::mem_row_major);
    __syncthreads();

#pragma unroll 4
    for (int u = tid; u < 8192; u += 256) {
        int r = u >> 6, c = u & 63;
        int n = bn + c;
        if (n >= N) continue;
        float v = stage[r * CST + c] + (bias ? bias[n] : 0.f);
        if (OUT_BF16) ((bf16*)Cout)[(size_t)(bm + r) * N + n] = __float2bfloat16(v);
        else          ((float*)Cout)[(size_t)(bm + r) * N + n] = v;
    }
}

// ---------------- depthwise causal conv1d + silu --------------------------------
__global__ void conv1d_silu_kernel(const float* __restrict__ cw, const float* __restrict__ cb) {
    int gid = blockIdx.x * 256 + threadIdx.x;
    if (gid >= ROWS * DI) return;
    int idx = gid / DI, d = gid - idx * DI;
    int l = idx & 1023;
    float s = cb[d];
#pragma unroll
    for (int k = 0; k < 4; k++) {
        int ll = l - 3 + k;
        if (ll >= 0)
            s = fmaf(g_xz[(size_t)(idx - 3 + k) * 768 + d], cw[d * 4 + k], s);
    }
    float r = s / (1.f + expf(-s));
    g_uact[gid] = r;
    g_uactb[gid] = __float2bfloat16(r);
}

// ---------------- dt_proj + softplus -------------------------------------------
__global__ void dtproj_kernel(const float* __restrict__ dpw, const float* __restrict__ dpb) {
    int idx = blockIdx.x;
    int d = threadIdx.x;
    __shared__ float dts[DTR];
    if (d < DTR) dts[d] = g_dbc[idx * DBC_N + d];
    __syncthreads();
    float s = dpb[d];
#pragma unroll
    for (int r = 0; r < DTR; r++) s = fmaf(dts[r], dpw[d * DTR + r], s);
    g_delta[(size_t)idx * DI + d] = fmaxf(s, 0.f) + log1pf(expf(-fabsf(s)));
}

// ---------------- selective scan ------------------------------------------------
__global__ __launch_bounds__(256)
void scan_kernel(const float* __restrict__ A_log, const float* __restrict__ Dv) {
    int tid = threadIdx.x;
    int g = blockIdx.x * 16 + (tid >> 4);
    int lane = tid & 15;
    int b = g / DI, d = g - b * DI;
    float An = -expf(A_log[d * DS + lane]);
    float Dd = Dv[d];
    float h = 0.f;
    int base = b * LSEQ;
    for (int l = 0; l < LSEQ; l++) {
        int idx = base + l;
        float delta = g_delta[(size_t)idx * DI + d];
        float uu    = g_uact [(size_t)idx * DI + d];
        float Bn    = g_dbc[idx * DBC_N + DTR + lane];
        float Cn    = g_dbc[idx * DBC_N + DTR + DS + lane];
        h = fmaf(expf(delta * An), h, delta * Bn * uu);
        float t = h * Cn;
        t += __shfl_xor_sync(0xffffffffu, t, 8);
        t += __shfl_xor_sync(0xffffffffu, t, 4);
        t += __shfl_xor_sync(0xffffffffu, t, 2);
        t += __shfl_xor_sync(0xffffffffu, t, 1);
        if (lane == 0) {
            float z = g_xz[(size_t)idx * 768 + DI + d];
            float y = fmaf(uu, Dd, t);
            g_ygb[(size_t)idx * DI + d] = __float2bfloat16(y * (z / (1.f + expf(-z))));
        }
    }
}

// ---------------- WMMA bf16 deconv GEMM (2 CTA/SM) ------------------------------
#define ASTRIDE 200
#define SSTRIDE 132
__global__ __launch_bounds__(256, 2)
void deconv_wmma_kernel(const bf16* __restrict__ G, const bf16* __restrict__ Wt,
                        const float* __restrict__ bias, bf16* __restrict__ out)
{
    extern __shared__ char smem[];
    bf16* As = (bf16*)smem;
    bf16* Bs = As + 128 * ASTRIDE;
    float* stage = (float*)smem;

    int tid = threadIdx.x;
    int bn = blockIdx.x * 128, bm = blockIdx.y * 128;

    {
        const char* gsrc = (const char*)(G + (size_t)bm * DM);
        const char* wsrc = (const char*)(Wt + (size_t)bn * DM);
#pragma unroll 4
        for (int u = tid; u < 3072; u += 256) {
            int r = u / 24, j = u % 24;
            *(float4*)((char*)As + r * (ASTRIDE * 2) + j * 16) =
                *(const float4*)(gsrc + r * 384 + j * 16);
            *(float4*)((char*)Bs + r * (ASTRIDE * 2) + j * 16) =
                *(const float4*)(wsrc + r * 384 + j * 16);
        }
    }
    __syncthreads();

    int wid = tid >> 5;
    int wm = (wid >> 1) * 32, wn = (wid & 1) * 64;

    wmma::fragment<wmma::accumulator, 16, 16, 16, float> acc[2][4];
#pragma unroll
    for (int i = 0; i < 2; i++)
#pragma unroll
        for (int j = 0; j < 4; j++) wmma::fill_fragment(acc[i][j], 0.f);

#pragma unroll
    for (int k = 0; k < DM; k += 16) {
        wmma::fragment<wmma::matrix_a, 16, 16, 16, bf16, wmma::row_major> af[2];
        wmma::fragment<wmma::matrix_b, 16, 16, 16, bf16, wmma::col_major> bf_[4];
#pragma unroll
        for (int i = 0; i < 2; i++)
            wmma::load_matrix_sync(af[i], As + (wm + i * 16) * ASTRIDE + k, ASTRIDE);
#pragma unroll
        for (int j = 0; j < 4; j++)
            wmma::load_matrix_sync(bf_[j], Bs + (wn + j * 16) * ASTRIDE + k, ASTRIDE);
#pragma unroll
        for (int i = 0; i < 2; i++)
#pragma unroll
            for (int j = 0; j < 4; j++)
                wmma::mma_sync(acc[i][j], af[i], bf_[j], acc[i][j]);
    }
    __syncthreads();

#pragma unroll
    for (int i = 0; i < 2; i++)
#pragma unroll
        for (int j = 0; j < 4; j++)
            wmma::store_matrix_sync(stage + (wm + i * 16) * SSTRIDE + wn + j * 16,
                                    acc[i][j], SSTRIDE, wmma::mem_row_major);
    __syncthreads();

    {
        int b_img  = bm >> 10;
        int h_base = (bm & 1023) >> 5;
        int dch    = bn >> 8;
        int p_base = (bn >> 4) & 15;
        float bv = bias[dch];
        bf16* dst = out + (size_t)b_img * 16777216 + (size_t)dch * 262144;
#pragma unroll 4
        for (int i = tid; i < 2048; i += 256) {
            int row = i >> 6;
            int c8  = (i & 63) * 8;
            int h = row >> 3, p = row & 7;
            int w = c8 >> 4, q = c8 & 15;
            const float* sp = stage + (h * 32 + w) * SSTRIDE + p * 16 + q;
            float4 v0 = *(const float4*)sp;
            float4 v1 = *(const float4*)(sp + 4);
            __nv_bfloat162 o0 = __floats2bfloat162_rn(fmaxf(v0.x + bv, 0.f), fmaxf(v0.y + bv, 0.f));
            __nv_bfloat162 o1 = __floats2bfloat162_rn(fmaxf(v0.z + bv, 0.f), fmaxf(v0.w + bv, 0.f));
            __nv_bfloat162 o2 = __floats2bfloat162_rn(fmaxf(v1.x + bv, 0.f), fmaxf(v1.y + bv, 0.f));
            __nv_bfloat162 o3 = __floats2bfloat162_rn(fmaxf(v1.z + bv, 0.f), fmaxf(v1.w + bv, 0.f));
            uint4 pkv;
            pkv.x = *(uint32_t*)&o0; pkv.y = *(uint32_t*)&o1;
            pkv.z = *(uint32_t*)&o2; pkv.w = *(uint32_t*)&o3;
            *(uint4*)(dst + (size_t)((h_base + h) * 16 + p_base + p) * 512 + c8) = pkv;
        }
    }
}

// ---------------- 3x3 conv + bias + sigmoid, packed f32x2, 4px/thread -----------
// block 256 thr (16x16), tile 64 wide x 16 high, 8-channel chunks.
#define C3_TS 68     // tile row stride (floats), cols 0..67 cover x0'..x0'+67
__global__ __launch_bounds__(256)
void conv3_sigmoid_kernel(const float* __restrict__ W, const float* __restrict__ wb,
                          float* __restrict__ out) {
    extern __shared__ char c3sm[];
    u64*   ws2  = (u64*)c3sm;                 // 1728 packed weight pairs
    float* tile = (float*)(c3sm + 1728 * 8);  // 8 x 18 x C3_TS

    int b = blockIdx.z, th = blockIdx.y, tw = blockIdx.x;
    int tid = threadIdx.x;
    for (int i = tid; i < 1728; i += 256) { float w = W[i]; ws2[i] = pk2(w, w); }

    int py = tid >> 4, px = tid & 15;
    int y0 = th * 16 - 1;
    int x0 = tw * 64 - 2;     // even -> uint-pair gmem loads aligned

    u64 accA[3], accB[3];
#pragma unroll
    for (int oc = 0; oc < 3; oc++) { accA[oc] = pk2(wb[oc], wb[oc]); accB[oc] = accA[oc]; }

    for (int c0 = 0; c0 < 64; c0 += 8) {
        __syncthreads();
        // load 8 channels x 18 rows x 68 cols (34 bf16-pairs per row)
        for (int i = tid; i < 8 * 18 * 34; i += 256) {
            int dl = i / (18 * 34), rem = i - dl * (18 * 34);
            int r = rem / 34, j = rem - r * 34;
            int yy = y0 + r, xx = x0 + j * 2;
            float f0 = 0.f, f1 = 0.f;
            if (yy >= 0 && yy < 512) {
                const bf16* src = g_decb + (((size_t)b * 64 + c0 + dl) * 512 + yy) * 512;
                if (xx >= 0 && xx + 1 < 512) {
                    __nv_bfloat162 v = *(const __nv_bfloat162*)(src + xx);
                    f0 = __bfloat162float(v.x); f1 = __bfloat162float(v.y);
                } else {
                    if (xx >= 0 && xx < 512)         f0 = __bfloat162float(src[xx]);
                    if (xx + 1 >= 0 && xx + 1 < 512) f1 = __bfloat162float(src[xx + 1]);
                }
            }
            float* t = tile + (dl * 18 + r) * C3_TS + j * 2;
            t[0] = f0; t[1] = f1;
        }
        __syncthreads();

#pragma unroll
        for (int dl = 0; dl < 8; dl++) {
            int d = c0 + dl;
            const u64* w0 = ws2 + d * 9;
            const u64* w1 = ws2 + (64 + d) * 9;
            const u64* w2 = ws2 + (128 + d) * 9;
            const float* trow = tile + dl * 18 * C3_TS + px * 4 + 1;
#pragma unroll
            for (int dy = 0; dy < 3; dy++) {
                const float* t = trow + (py + dy) * C3_TS;
                float v0 = t[0], v1 = t[1], v2 = t[2], v3 = t[3], v4 = t[4], v5 = t[5];
                u64 p01 = pk2(v0, v1), p12 = pk2(v1, v2), p23 = pk2(v2, v3);
                u64 p34 = pk2(v3, v4), p45 = pk2(v4, v5);
                int wi = dy * 3;
                fma2(accA[0], p01, w0[wi]); fma2(accA[0], p12, w0[wi+1]); fma2(accA[0], p23, w0[wi+2]);
                fma2(accA[1], p01, w1[wi]); fma2(accA[1], p12, w1[wi+1]); fma2(accA[1], p23, w1[wi+2]);
                fma2(accA[2], p01, w2[wi]); fma2(accA[2], p12, w2[wi+1]); fma2(accA[2], p23, w2[wi+2]);
                fma2(accB[0], p23, w0[wi]); fma2(accB[0], p34, w0[wi+1]); fma2(accB[0], p45, w0[wi+2]);
                fma2(accB[1], p23, w1[wi]); fma2(accB[1], p34, w1[wi+1]); fma2(accB[1], p45, w1[wi+2]);
                fma2(accB[2], p23, w2[wi]); fma2(accB[2], p34, w2[wi+1]); fma2(accB[2], p45, w2[wi+2]);
            }
        }
    }

    int Y = th * 16 + py, X0 = tw * 64 + px * 4;
    size_t o = (size_t)b * 3 * 262144 + (size_t)Y * 512 + X0;
#pragma unroll
    for (int oc = 0; oc < 3; oc++) {
        float a0, a1, a2, a3;
        unpk2(a0, a1, accA[oc]);
        unpk2(a2, a3, accB[oc]);
        float* dst = out + o + (size_t)oc * 262144;
        dst[0] = 1.f / (1.f + expf(-a0));
        dst[1] = 1.f / (1.f + expf(-a1));
        dst[2] = 1.f / (1.f + expf(-a2));
        dst[3] = 1.f / (1.f + expf(-a3));
    }
}

// ---------------- launch --------------------------------------------------------
extern "C" void kernel_launch(void* const* d_in, const int* in_sizes, int n_in,
                              void* d_out, int out_size) {
    const float* x         = (const float*)d_in[0];
    const float* patch_w   = (const float*)d_in[1];
    const float* patch_b   = (const float*)d_in[2];
    const float* in_proj_w = (const float*)d_in[3];
    const float* conv1d_w  = (const float*)d_in[4];
    const float* conv1d_b  = (const float*)d_in[5];
    const float* x_proj_w  = (const float*)d_in[6];
    const float* dt_proj_w = (const float*)d_in[7];
    const float* dt_proj_b = (const float*)d_in[8];
    const float* A_log     = (const float*)d_in[9];
    const float* Dv        = (const float*)d_in[10];
    const float* out_proj_w= (const float*)d_in[11];
    const float* deconv_w  = (const float*)d_in[12];
    const float* deconv_b  = (const float*)d_in[13];
    const float* dec_conv_w= (const float*)d_in[14];
    const float* dec_conv_b= (const float*)d_in[15];
    float* out = (float*)d_out;

    bf16 *Apeb, *seqb, *uactb, *ygb, *goutb, *wtb, *decb, *pwb, *ipwb, *xpwb, *opwb;
    float *xz, *uact, *dbc, *delta;
    cudaGetSymbolAddress((void**)&Apeb, g_Apeb);
    cudaGetSymbolAddress((void**)&seqb, g_seqb);
    cudaGetSymbolAddress((void**)&xz,   g_xz);
    cudaGetSymbolAddress((void**)&uact, g_uact);
    cudaGetSymbolAddress((void**)&uactb,g_uactb);
    cudaGetSymbolAddress((void**)&dbc,  g_dbc);
    cudaGetSymbolAddress((void**)&delta,g_delta);
    cudaGetSymbolAddress((void**)&ygb,  g_ygb);
    cudaGetSymbolAddress((void**)&goutb,g_goutb);
    cudaGetSymbolAddress((void**)&wtb,  g_wtb);
    cudaGetSymbolAddress((void**)&decb, g_decb);
    cudaGetSymbolAddress((void**)&pwb,  g_pwb);
    cudaGetSymbolAddress((void**)&ipwb, g_ipwb);
    cudaGetSymbolAddress((void**)&xpwb, g_xpwb);
    cudaGetSymbolAddress((void**)&opwb, g_opwb);

    const int DSMEM = 2 * 128 * ASTRIDE * 2;                 // 102400
    const int C3SMEM = 1728 * 8 + 8 * 18 * C3_TS * 4;        // 52992
    cudaFuncSetAttribute(deconv_wmma_kernel,
                         cudaFuncAttributeMaxDynamicSharedMemorySize, DSMEM);
    cudaFuncSetAttribute(conv3_sigmoid_kernel,
                         cudaFuncAttributeMaxDynamicSharedMemorySize, C3SMEM);

    cvt_kernel<<<(DM*768 + 255)/256, 256>>>(patch_w, pwb, DM*768);
    cvt_kernel<<<(2*DI*DM + 255)/256, 256>>>(in_proj_w, ipwb, 2*DI*DM);
    cvt_kernel<<<(DBC_N*DI + 255)/256, 256>>>(x_proj_w, xpwb, DBC_N*DI);
    cvt_kernel<<<(DM*DI + 255)/256, 256>>>(out_proj_w, opwb, DM*DI);
    transpose_w_kernel<<<(DM * NDEC + 255) / 256, 256>>>(deconv_w);

    im2col_kernel<<<(ROWS * 768 + 255) / 256, 256>>>(x);
    wgemm_kernel<true><<<dim3(3, 64), 256>>>(Apeb, pwb, patch_b, seqb, DM, 768);
    wgemm_kernel<false><<<dim3(12, 64), 256>>>(seqb, ipwb, nullptr, xz, 2 * DI, DM);
    conv1d_silu_kernel<<<(ROWS * DI + 255) / 256, 256>>>(conv1d_w, conv1d_b);
    wgemm_kernel<false><<<dim3(1, 64), 256>>>(uactb, xpwb, nullptr, dbc, DBC_N, DI);
    dtproj_kernel<<<ROWS, DI>>>(dt_proj_w, dt_proj_b);
    scan_kernel<<<(BATCH * DI) / 16, 256>>>(A_log, Dv);
    wgemm_kernel<true><<<dim3(3, 64), 256>>>(ygb, opwb, nullptr, goutb, DM, DI);
    deconv_wmma_kernel<<<dim3(128, 64), 256, DSMEM>>>(goutb, wtb, deconv_b, decb);
    conv3_sigmoid_kernel<<<dim3(8, 32, 8), 256, C3SMEM>>>(dec_conv_w, dec_conv_b, out);
}

// round 6
// speedup vs baseline: 2.3504x; 1.0034x over previous
#include <cuda_runtime.h>
#include <cuda_bf16.h>
#include <mma.h>
#include <math.h>
#include <stdint.h>

using namespace nvcuda;

#define BATCH 8
#define LSEQ  1024
#define ROWS  (BATCH*LSEQ)   // 8192
#define DM    192
#define DI    384
#define DS    16
#define DTR   12
#define DBC_N (DTR + 2*DS)   // 44
#define NDEC  16384

typedef __nv_bfloat16 bf16;
typedef unsigned long long u64;

// ---------------- scratch -------------------------------------------------------
__device__ bf16  g_Apeb[ROWS*768];
__device__ bf16  g_seqb[ROWS*DM];
__device__ float g_xz  [ROWS*2*DI];
__device__ float g_uact[ROWS*DI];
__device__ bf16  g_uactb[ROWS*DI];
__device__ float g_dbc [ROWS*DBC_N];
__device__ float g_delta[ROWS*DI];
__device__ bf16  g_ygb [ROWS*DI];
__device__ bf16  g_goutb[ROWS*DM];
__device__ bf16  g_wtb [(size_t)NDEC*DM];
__device__ bf16  g_decb[(size_t)BATCH*64*512*512];   // 268 MB
__device__ bf16  g_pwb [DM*768];
__device__ bf16  g_ipwb[2*DI*DM];
__device__ bf16  g_xpwb[DBC_N*DI];
__device__ bf16  g_opwb[DM*DI];

// ---------------- packed f32x2 helpers ------------------------------------------
__device__ __forceinline__ u64 pk2(float lo, float hi) {
    u64 r; asm("mov.b64 %0, {%1, %2};" : "=l"(r) : "f"(lo), "f"(hi)); return r;
}
__device__ __forceinline__ void unpk2(float& lo, float& hi, u64 v) {
    asm("mov.b64 {%0, %1}, %2;" : "=f"(lo), "=f"(hi) : "l"(v));
}
__device__ __forceinline__ void fma2(u64& acc, u64 a, u64 b) {
    asm("fma.rn.f32x2 %0, %1, %2, %0;" : "+l"(acc) : "l"(a), "l"(b));
}

// ---------------- merged weight converts ----------------------------------------
// ranges: [0, DM*768) -> pwb ; next 2*DI*DM -> ipwb ; next DBC_N*DI -> xpwb ;
// next DM*DI -> opwb
#define W0 (DM*768)
#define W1 (W0 + 2*DI*DM)
#define W2 (W1 + DBC_N*DI)
#define W3 (W2 + DM*DI)
__global__ void cvt_weights_kernel(const float* __restrict__ pw, const float* __restrict__ ipw,
                                   const float* __restrict__ xpw, const float* __restrict__ opw) {
    int i = blockIdx.x * 256 + threadIdx.x;
    if (i >= W3) return;
    if (i < W0)      g_pwb [i]      = __float2bfloat16(pw [i]);
    else if (i < W1) g_ipwb[i - W0] = __float2bfloat16(ipw[i - W0]);
    else if (i < W2) g_xpwb[i - W1] = __float2bfloat16(xpw[i - W1]);
    else             g_opwb[i - W2] = __float2bfloat16(opw[i - W2]);
}
__global__ void transpose_w_kernel(const float* __restrict__ W) {
    int i = blockIdx.x * 256 + threadIdx.x;
    if (i >= DM * NDEC) return;
    int n = i / DM, k = i - n * DM;
    g_wtb[(size_t)n * DM + k] = __float2bfloat16(W[(size_t)k * NDEC + n]);
}

// ---------------- im2col (writes bf16) ------------------------------------------
__global__ void im2col_kernel(const float* __restrict__ x) {
    int gid = blockIdx.x * 256 + threadIdx.x;
    if (gid >= ROWS * 768) return;
    int row = gid / 768, k = gid - row * 768;
    int c = k >> 8, rem = k & 255, p = rem >> 4, q = rem & 15;
    int b = row >> 10, hw = row & 1023, h = hw >> 5, w = hw & 31;
    g_Apeb[gid] = __float2bfloat16(x[((b * 3 + c) * 512 + h * 16 + p) * 512 + w * 16 + q]);
}

// ---------------- generic WMMA bf16 NT GEMM -------------------------------------
#define AST 72
#define CST 68
template<bool OUT_BF16>
__global__ __launch_bounds__(256)
void wgemm_kernel(const bf16* __restrict__ A, const bf16* __restrict__ B,
                  const float* __restrict__ bias, void* __restrict__ Cout,
                  int N, int K)
{
    __shared__ __align__(16) char sm[34816];
    bf16* As = (bf16*)sm;
    bf16* Bs = As + 128 * AST;
    float* stage = (float*)sm;

    int tid = threadIdx.x;
    int bm = blockIdx.y * 128, bn = blockIdx.x * 64;
    int wid = tid >> 5;
    int wm = (wid >> 1) * 32, wn = (wid & 1) * 32;

    wmma::fragment<wmma::accumulator, 16, 16, 16, float> acc[2][2];
#pragma unroll
    for (int i = 0; i < 2; i++)
#pragma unroll
        for (int j = 0; j < 2; j++) wmma::fill_fragment(acc[i][j], 0.f);

    for (int k0 = 0; k0 < K; k0 += 64) {
#pragma unroll 4
        for (int u = tid; u < 1024; u += 256) {
            int r = u >> 3, j = u & 7;
            *(float4*)((char*)As + r * (AST * 2) + j * 16) =
                *(const float4*)(A + (size_t)(bm + r) * K + k0 + j * 8);
        }
#pragma unroll 2
        for (int u = tid; u < 512; u += 256) {
            int r = u >> 3, j = u & 7;
            float4 v = make_float4(0.f, 0.f, 0.f, 0.f);
            if (bn + r < N)
                v = *(const float4*)(B + (size_t)(bn + r) * K + k0 + j * 8);
            *(float4*)((char*)Bs + r * (AST * 2) + j * 16) = v;
        }
        __syncthreads();
#pragma unroll
        for (int kk = 0; kk < 4; kk++) {
            wmma::fragment<wmma::matrix_a, 16, 16, 16, bf16, wmma::row_major> af[2];
#pragma unroll
            for (int i = 0; i < 2; i++)
                wmma::load_matrix_sync(af[i], As + (wm + i * 16) * AST + kk * 16, AST);
#pragma unroll
            for (int j = 0; j < 2; j++) {
                wmma::fragment<wmma::matrix_b, 16, 16, 16, bf16, wmma::col_major> bfj;
                wmma::load_matrix_sync(bfj, Bs + (wn + j * 16) * AST + kk * 16, AST);
                wmma::mma_sync(acc[0][j], af[0], bfj, acc[0][j]);
                wmma::mma_sync(acc[1][j], af[1], bfj, acc[1][j]);
            }
        }
        __syncthreads();
    }

#pragma unroll
    for (int i = 0; i < 2; i++)
#pragma unroll
        for (int j = 0; j < 2; j++)
            wmma::store_matrix_sync(stage + (wm + i * 16) * CST + wn + j * 16,
                                    acc[i][j], CST, wmma::mem_row_major);
    __syncthreads();

#pragma unroll 4
    for (int u = tid; u < 8192; u += 256) {
        int r = u >> 6, c = u & 63;
        int n = bn + c;
        if (n >= N) continue;
        float v = stage[r * CST + c] + (bias ? bias[n] : 0.f);
        if (OUT_BF16) ((bf16*)Cout)[(size_t)(bm + r) * N + n] = __float2bfloat16(v);
        else          ((float*)Cout)[(size_t)(bm + r) * N + n] = v;
    }
}

// ---------------- depthwise causal conv1d + silu --------------------------------
__global__ void conv1d_silu_kernel(const float* __restrict__ cw, const float* __restrict__ cb) {
    int gid = blockIdx.x * 256 + threadIdx.x;
    if (gid >= ROWS * DI) return;
    int idx = gid / DI, d = gid - idx * DI;
    int l = idx & 1023;
    float s = cb[d];
#pragma unroll
    for (int k = 0; k < 4; k++) {
        int ll = l - 3 + k;
        if (ll >= 0)
            s = fmaf(g_xz[(size_t)(idx - 3 + k) * 768 + d], cw[d * 4 + k], s);
    }
    float r = s / (1.f + expf(-s));
    g_uact[gid] = r;
    g_uactb[gid] = __float2bfloat16(r);
}

// ---------------- dt_proj + softplus -------------------------------------------
__global__ void dtproj_kernel(const float* __restrict__ dpw, const float* __restrict__ dpb) {
    int idx = blockIdx.x;
    int d = threadIdx.x;
    __shared__ float dts[DTR];
    if (d < DTR) dts[d] = g_dbc[idx * DBC_N + d];
    __syncthreads();
    float s = dpb[d];
#pragma unroll
    for (int r = 0; r < DTR; r++) s = fmaf(dts[r], dpw[d * DTR + r], s);
    g_delta[(size_t)idx * DI + d] = fmaxf(s, 0.f) + log1pf(expf(-fabsf(s)));
}

// ---------------- selective scan ------------------------------------------------
__global__ __launch_bounds__(256)
void scan_kernel(const float* __restrict__ A_log, const float* __restrict__ Dv) {
    int tid = threadIdx.x;
    int g = blockIdx.x * 16 + (tid >> 4);
    int lane = tid & 15;
    int b = g / DI, d = g - b * DI;
    float An = -expf(A_log[d * DS + lane]);
    float Dd = Dv[d];
    float h = 0.f;
    int base = b * LSEQ;
    for (int l = 0; l < LSEQ; l++) {
        int idx = base + l;
        float delta = g_delta[(size_t)idx * DI + d];
        float uu    = g_uact [(size_t)idx * DI + d];
        float Bn    = g_dbc[idx * DBC_N + DTR + lane];
        float Cn    = g_dbc[idx * DBC_N + DTR + DS + lane];
        h = fmaf(expf(delta * An), h, delta * Bn * uu);
        float t = h * Cn;
        t += __shfl_xor_sync(0xffffffffu, t, 8);
        t += __shfl_xor_sync(0xffffffffu, t, 4);
        t += __shfl_xor_sync(0xffffffffu, t, 2);
        t += __shfl_xor_sync(0xffffffffu, t, 1);
        if (lane == 0) {
            float z = g_xz[(size_t)idx * 768 + DI + d];
            float y = fmaf(uu, Dd, t);
            g_ygb[(size_t)idx * DI + d] = __float2bfloat16(y * (z / (1.f + expf(-z))));
        }
    }
}

// ---------------- WMMA bf16 deconv GEMM (2 CTA/SM, spill-free) ------------------
#define ASTRIDE 200
#define SSTRIDE 132
__global__ __launch_bounds__(256, 2)
void deconv_wmma_kernel(const bf16* __restrict__ G, const bf16* __restrict__ Wt,
                        const float* __restrict__ bias, bf16* __restrict__ out)
{
    extern __shared__ char smem[];
    bf16* As = (bf16*)smem;
    bf16* Bs = As + 128 * ASTRIDE;
    float* stage = (float*)smem;

    int tid = threadIdx.x;
    int bn = blockIdx.x * 128, bm = blockIdx.y * 128;

    {
        const char* gsrc = (const char*)(G + (size_t)bm * DM);
        const char* wsrc = (const char*)(Wt + (size_t)bn * DM);
#pragma unroll 4
        for (int u = tid; u < 3072; u += 256) {
            int r = u / 24, j = u % 24;
            *(float4*)((char*)As + r * (ASTRIDE * 2) + j * 16) =
                *(const float4*)(gsrc + r * 384 + j * 16);
            *(float4*)((char*)Bs + r * (ASTRIDE * 2) + j * 16) =
                *(const float4*)(wsrc + r * 384 + j * 16);
        }
    }
    __syncthreads();

    int wid = tid >> 5;
    int wm = (wid >> 1) * 32, wn = (wid & 1) * 64;

    wmma::fragment<wmma::accumulator, 16, 16, 16, float> acc[2][4];
#pragma unroll
    for (int i = 0; i < 2; i++)
#pragma unroll
        for (int j = 0; j < 4; j++) wmma::fill_fragment(acc[i][j], 0.f);

    // register-lean MMA loop: only ONE b-fragment live at a time
#pragma unroll
    for (int k = 0; k < DM; k += 16) {
        wmma::fragment<wmma::matrix_a, 16, 16, 16, bf16, wmma::row_major> af[2];
#pragma unroll
        for (int i = 0; i < 2; i++)
            wmma::load_matrix_sync(af[i], As + (wm + i * 16) * ASTRIDE + k, ASTRIDE);
#pragma unroll
        for (int j = 0; j < 4; j++) {
            wmma::fragment<wmma::matrix_b, 16, 16, 16, bf16, wmma::col_major> bfj;
            wmma::load_matrix_sync(bfj, Bs + (wn + j * 16) * ASTRIDE + k, ASTRIDE);
            wmma::mma_sync(acc[0][j], af[0], bfj, acc[0][j]);
            wmma::mma_sync(acc[1][j], af[1], bfj, acc[1][j]);
        }
    }
    __syncthreads();

#pragma unroll
    for (int i = 0; i < 2; i++)
#pragma unroll
        for (int j = 0; j < 4; j++)
            wmma::store_matrix_sync(stage + (wm + i * 16) * SSTRIDE + wn + j * 16,
                                    acc[i][j], SSTRIDE, wmma::mem_row_major);
    __syncthreads();

    {
        int b_img  = bm >> 10;
        int h_base = (bm & 1023) >> 5;
        int dch    = bn >> 8;
        int p_base = (bn >> 4) & 15;
        float bv = bias[dch];
        bf16* dst = out + (size_t)b_img * 16777216 + (size_t)dch * 262144;
#pragma unroll 4
        for (int i = tid; i < 2048; i += 256) {
            int row = i >> 6;
            int c8  = (i & 63) * 8;
            int h = row >> 3, p = row & 7;
            int w = c8 >> 4, q = c8 & 15;
            const float* sp = stage + (h * 32 + w) * SSTRIDE + p * 16 + q;
            float4 v0 = *(const float4*)sp;
            float4 v1 = *(const float4*)(sp + 4);
            __nv_bfloat162 o0 = __floats2bfloat162_rn(fmaxf(v0.x + bv, 0.f), fmaxf(v0.y + bv, 0.f));
            __nv_bfloat162 o1 = __floats2bfloat162_rn(fmaxf(v0.z + bv, 0.f), fmaxf(v0.w + bv, 0.f));
            __nv_bfloat162 o2 = __floats2bfloat162_rn(fmaxf(v1.x + bv, 0.f), fmaxf(v1.y + bv, 0.f));
            __nv_bfloat162 o3 = __floats2bfloat162_rn(fmaxf(v1.z + bv, 0.f), fmaxf(v1.w + bv, 0.f));
            uint4 pkv;
            pkv.x = *(uint32_t*)&o0; pkv.y = *(uint32_t*)&o1;
            pkv.z = *(uint32_t*)&o2; pkv.w = *(uint32_t*)&o3;
            *(uint4*)(dst + (size_t)((h_base + h) * 16 + p_base + p) * 512 + c8) = pkv;
        }
    }
}

// ---------------- 3x3 conv + bias + sigmoid, packed f32x2, 4px/thread -----------
#define C3_TS 68
__global__ __launch_bounds__(256)
void conv3_sigmoid_kernel(const float* __restrict__ W, const float* __restrict__ wb,
                          float* __restrict__ out) {
    extern __shared__ char c3sm[];
    u64*   ws2  = (u64*)c3sm;
    float* tile = (float*)(c3sm + 1728 * 8);

    int b = blockIdx.z, th = blockIdx.y, tw = blockIdx.x;
    int tid = threadIdx.x;
    for (int i = tid; i < 1728; i += 256) { float w = W[i]; ws2[i] = pk2(w, w); }

    int py = tid >> 4, px = tid & 15;
    int y0 = th * 16 - 1;
    int x0 = tw * 64 - 2;

    u64 accA[3], accB[3];
#pragma unroll
    for (int oc = 0; oc < 3; oc++) { accA[oc] = pk2(wb[oc], wb[oc]); accB[oc] = accA[oc]; }

    for (int c0 = 0; c0 < 64; c0 += 8) {
        __syncthreads();
        for (int i = tid; i < 8 * 18 * 34; i += 256) {
            int dl = i / (18 * 34), rem = i - dl * (18 * 34);
            int r = rem / 34, j = rem - r * 34;
            int yy = y0 + r, xx = x0 + j * 2;
            float f0 = 0.f, f1 = 0.f;
            if (yy >= 0 && yy < 512) {
                const bf16* src = g_decb + (((size_t)b * 64 + c0 + dl) * 512 + yy) * 512;
                if (xx >= 0 && xx + 1 < 512) {
                    __nv_bfloat162 v = *(const __nv_bfloat162*)(src + xx);
                    f0 = __bfloat162float(v.x); f1 = __bfloat162float(v.y);
                } else {
                    if (xx >= 0 && xx < 512)         f0 = __bfloat162float(src[xx]);
                    if (xx + 1 >= 0 && xx + 1 < 512) f1 = __bfloat162float(src[xx + 1]);
                }
            }
            float* t = tile + (dl * 18 + r) * C3_TS + j * 2;
            t[0] = f0; t[1] = f1;
        }
        __syncthreads();

#pragma unroll
        for (int dl = 0; dl < 8; dl++) {
            int d = c0 + dl;
            const u64* w0 = ws2 + d * 9;
            const u64* w1 = ws2 + (64 + d) * 9;
            const u64* w2 = ws2 + (128 + d) * 9;
            const float* trow = tile + dl * 18 * C3_TS + px * 4 + 1;
#pragma unroll
            for (int dy = 0; dy < 3; dy++) {
                const float* t = trow + (py + dy) * C3_TS;
                float v0 = t[0], v1 = t[1], v2 = t[2], v3 = t[3], v4 = t[4], v5 = t[5];
                u64 p01 = pk2(v0, v1), p12 = pk2(v1, v2), p23 = pk2(v2, v3);
                u64 p34 = pk2(v3, v4), p45 = pk2(v4, v5);
                int wi = dy * 3;
                fma2(accA[0], p01, w0[wi]); fma2(accA[0], p12, w0[wi+1]); fma2(accA[0], p23, w0[wi+2]);
                fma2(accA[1], p01, w1[wi]); fma2(accA[1], p12, w1[wi+1]); fma2(accA[1], p23, w1[wi+2]);
                fma2(accA[2], p01, w2[wi]); fma2(accA[2], p12, w2[wi+1]); fma2(accA[2], p23, w2[wi+2]);
                fma2(accB[0], p23, w0[wi]); fma2(accB[0], p34, w0[wi+1]); fma2(accB[0], p45, w0[wi+2]);
                fma2(accB[1], p23, w1[wi]); fma2(accB[1], p34, w1[wi+1]); fma2(accB[1], p45, w1[wi+2]);
                fma2(accB[2], p23, w2[wi]); fma2(accB[2], p34, w2[wi+1]); fma2(accB[2], p45, w2[wi+2]);
            }
        }
    }

    int Y = th * 16 + py, X0 = tw * 64 + px * 4;
    size_t o = (size_t)b * 3 * 262144 + (size_t)Y * 512 + X0;
#pragma unroll
    for (int oc = 0; oc < 3; oc++) {
        float a0, a1, a2, a3;
        unpk2(a0, a1, accA[oc]);
        unpk2(a2, a3, accB[oc]);
        float* dst = out + o + (size_t)oc * 262144;
        dst[0] = 1.f / (1.f + expf(-a0));
        dst[1] = 1.f / (1.f + expf(-a1));
        dst[2] = 1.f / (1.f + expf(-a2));
        dst[3] = 1.f / (1.f + expf(-a3));
    }
}

// ---------------- launch --------------------------------------------------------
extern "C" void kernel_launch(void* const* d_in, const int* in_sizes, int n_in,
                              void* d_out, int out_size) {
    const float* x         = (const float*)d_in[0];
    const float* patch_w   = (const float*)d_in[1];
    const float* patch_b   = (const float*)d_in[2];
    const float* in_proj_w = (const float*)d_in[3];
    const float* conv1d_w  = (const float*)d_in[4];
    const float* conv1d_b  = (const float*)d_in[5];
    const float* x_proj_w  = (const float*)d_in[6];
    const float* dt_proj_w = (const float*)d_in[7];
    const float* dt_proj_b = (const float*)d_in[8];
    const float* A_log     = (const float*)d_in[9];
    const float* Dv        = (const float*)d_in[10];
    const float* out_proj_w= (const float*)d_in[11];
    const float* deconv_w  = (const float*)d_in[12];
    const float* deconv_b  = (const float*)d_in[13];
    const float* dec_conv_w= (const float*)d_in[14];
    const float* dec_conv_b= (const float*)d_in[15];
    float* out = (float*)d_out;

    bf16 *Apeb, *seqb, *uactb, *ygb, *goutb, *wtb, *decb, *pwb, *ipwb, *xpwb, *opwb;
    float *xz, *uact, *dbc, *delta;
    cudaGetSymbolAddress((void**)&Apeb, g_Apeb);
    cudaGetSymbolAddress((void**)&seqb, g_seqb);
    cudaGetSymbolAddress((void**)&xz,   g_xz);
    cudaGetSymbolAddress((void**)&uact, g_uact);
    cudaGetSymbolAddress((void**)&uactb,g_uactb);
    cudaGetSymbolAddress((void**)&dbc,  g_dbc);
    cudaGetSymbolAddress((void**)&delta,g_delta);
    cudaGetSymbolAddress((void**)&ygb,  g_ygb);
    cudaGetSymbolAddress((void**)&goutb,g_goutb);
    cudaGetSymbolAddress((void**)&wtb,  g_wtb);
    cudaGetSymbolAddress((void**)&decb, g_decb);
    cudaGetSymbolAddress((void**)&pwb,  g_pwb);
    cudaGetSymbolAddress((void**)&ipwb, g_ipwb);
    cudaGetSymbolAddress((void**)&xpwb, g_xpwb);
    cudaGetSymbolAddress((void**)&opwb, g_opwb);

    const int DSMEM = 2 * 128 * ASTRIDE * 2;                 // 102400
    const int C3SMEM = 1728 * 8 + 8 * 18 * C3_TS * 4;        // 52992
    cudaFuncSetAttribute(deconv_wmma_kernel,
                         cudaFuncAttributeMaxDynamicSharedMemorySize, DSMEM);
    cudaFuncSetAttribute(conv3_sigmoid_kernel,
                         cudaFuncAttributeMaxDynamicSharedMemorySize, C3SMEM);

    cvt_weights_kernel<<<(W3 + 255)/256, 256>>>(patch_w, in_proj_w, x_proj_w, out_proj_w);
    transpose_w_kernel<<<(DM * NDEC + 255) / 256, 256>>>(deconv_w);

    im2col_kernel<<<(ROWS * 768 + 255) / 256, 256>>>(x);
    wgemm_kernel<true><<<dim3(3, 64), 256>>>(Apeb, pwb, patch_b, seqb, DM, 768);
    wgemm_kernel<false><<<dim3(12, 64), 256>>>(seqb, ipwb, nullptr, xz, 2 * DI, DM);
    conv1d_silu_kernel<<<(ROWS * DI + 255) / 256, 256>>>(conv1d_w, conv1d_b);
    wgemm_kernel<false><<<dim3(1, 64), 256>>>(uactb, xpwb, nullptr, dbc, DBC_N, DI);
    dtproj_kernel<<<ROWS, DI>>>(dt_proj_w, dt_proj_b);
    scan_kernel<<<(BATCH * DI) / 16, 256>>>(A_log, Dv);
    wgemm_kernel<true><<<dim3(3, 64), 256>>>(ygb, opwb, nullptr, goutb, DM, DI);
    deconv_wmma_kernel<<<dim3(128, 64), 256, DSMEM>>>(goutb, wtb, deconv_b, decb);
    conv3_sigmoid_kernel<<<dim3(8, 32, 8), 256, C3SMEM>>>(dec_conv_w, dec_conv_b, out);
}